// round 7
// baseline (speedup 1.0000x reference)
#include <cuda_runtime.h>
#include <cuda_fp16.h>
#include <math.h>
#include <stdint.h>

#define LEN   3072
#define HID   3072
#define NH    24
#define HD    128
#define MLPD  12288
#define N1    (3*HID + MLPD)   // 21504
#define N2    (HID + MLPD)     // 15360
#define EPSF  1e-6f

// ---------------- scratch ----------------------------------------------------
__device__ float g_mod[3*HID];
__device__ __align__(256) float  g_proj[(size_t)LEN*N1];
__device__ __align__(256) __half g_a1[(size_t)LEN*HID];
__device__ __align__(256) __half g_w1[(size_t)N1*HID];
__device__ __align__(256) __half g_a2[(size_t)LEN*N2];
__device__ __align__(256) __half g_w2[(size_t)HID*N2];
__device__ __align__(256) __half g_qh[(size_t)NH*LEN*HD];
__device__ __align__(256) __half g_kh[(size_t)NH*LEN*HD];
__device__ __align__(256) __half g_vT[(size_t)NH*HD*LEN];
__device__ __align__(256) __half g_S[(size_t)NH*LEN*LEN];
__device__ __align__(256) __half g_P[(size_t)NH*LEN*LEN];
__device__ __align__(256) float  g_attn[(size_t)NH*LEN*HD];

__device__ __forceinline__ uint32_t smem_u32(const void* p) {
    uint32_t a;
    asm("{ .reg .u64 t; cvta.to.shared.u64 t, %1; cvt.u32.u64 %0, t; }" : "=r"(a) : "l"(p));
    return a;
}

#define PITCH 80                      // 64B data + 16B pad per 32-k row

// =============== GEMM A: 128x256 tile, 64x64 warp tiles, 4-stage =============
#define ATILE2 (128*PITCH)            // 10240
#define BTILE2 (256*PITCH)            // 20480
#define STGSZ2 (ATILE2 + BTILE2)      // 30720
#define NSTG2  4
#define SMEM2  (NSTG2*STGSZ2)         // 122880

template<bool OUTH, bool BIAS>
__global__ void __launch_bounds__(256, 1) gemm_w(
    const __half* __restrict__ A, const __half* __restrict__ B,
    const float* __restrict__ bias, void* __restrict__ Cv,
    int ldC, int K, float alpha, size_t sA, size_t sB, size_t sC)
{
    extern __shared__ char smem[];
    const uint32_t sb = smem_u32(smem);
    const int tid = threadIdx.x, lane = tid & 31, wid = tid >> 5;
    const int wm = wid & 1, wn = wid >> 1;             // 2m x 4n warps (64x64 tiles)
    const int m0 = blockIdx.x * 128, n0 = blockIdx.y * 256;
    A += (size_t)blockIdx.z * sA;
    B += (size_t)blockIdx.z * sB;
    const int KT = K >> 5;

    auto load_stage = [&](int buf, int kt) {
        const int k0 = kt << 5;
        #pragma unroll
        for (int i = 0; i < 6; i++) {                  // 1536 chunks of 16B
            int idx = tid + (i << 8);
            int isB = idx >= 512;
            int e = isB ? idx - 512 : idx;
            int r = e >> 2, ch = e & 3;
            const __half* src = (isB ? B + (size_t)(n0 + r) * K
                                     : A + (size_t)(m0 + r) * K) + k0 + ch * 8;
            uint32_t dst = sb + buf * STGSZ2 + isB * ATILE2 + r * PITCH + ch * 16;
            asm volatile("cp.async.cg.shared.global [%0], [%1], 16;"
                         :: "r"(dst), "l"(src) : "memory");
        }
    };

    float acc[4][8][4];
    #pragma unroll
    for (int a = 0; a < 4; a++)
        #pragma unroll
        for (int b = 0; b < 8; b++)
            #pragma unroll
            for (int c = 0; c < 4; c++) acc[a][b][c] = 0.f;

    const int aRow = (lane & 7) + ((lane >> 3) & 1) * 8, aK = (lane >> 4) * 16;
    const int bRow = (lane & 7) + (lane >> 4) * 8,       bK = ((lane >> 3) & 1) * 16;
    const uint32_t aAdr0 = (uint32_t)((wm * 64 + aRow) * PITCH + aK);
    const uint32_t bAdr0 = (uint32_t)(ATILE2 + (wn * 64 + bRow) * PITCH + bK);

    // prologue: 3 stages in flight
    #pragma unroll
    for (int s = 0; s < 3; s++) {
        if (s < KT) load_stage(s, s);
        asm volatile("cp.async.commit_group;" ::: "memory");
    }

    for (int kt = 0; kt < KT; kt++) {
        asm volatile("cp.async.wait_group 2;" ::: "memory");
        __syncthreads();
        int nk = kt + 3;
        if (nk < KT) load_stage(nk & (NSTG2 - 1), nk);
        asm volatile("cp.async.commit_group;" ::: "memory");

        const uint32_t base = sb + (kt & (NSTG2 - 1)) * STGSZ2;
        #pragma unroll
        for (int ks = 0; ks < 2; ks++) {
            uint32_t ra[4][4], rb[4][4];
            #pragma unroll
            for (int mt = 0; mt < 4; mt++) {
                uint32_t ad = base + aAdr0 + mt * (16 * PITCH) + ks * 32;
                asm volatile("ldmatrix.sync.aligned.m8n8.x4.shared.b16 {%0,%1,%2,%3}, [%4];"
                    : "=r"(ra[mt][0]), "=r"(ra[mt][1]), "=r"(ra[mt][2]), "=r"(ra[mt][3])
                    : "r"(ad));
            }
            #pragma unroll
            for (int nt = 0; nt < 4; nt++) {
                uint32_t bd = base + bAdr0 + nt * (16 * PITCH) + ks * 32;
                asm volatile("ldmatrix.sync.aligned.m8n8.x4.shared.b16 {%0,%1,%2,%3}, [%4];"
                    : "=r"(rb[nt][0]), "=r"(rb[nt][1]), "=r"(rb[nt][2]), "=r"(rb[nt][3])
                    : "r"(bd));
            }
            #pragma unroll
            for (int mt = 0; mt < 4; mt++)
                #pragma unroll
                for (int nt = 0; nt < 4; nt++) {
                    #pragma unroll
                    for (int h = 0; h < 2; h++) {
                        float* c = acc[mt][nt * 2 + h];
                        asm volatile(
                            "mma.sync.aligned.m16n8k16.row.col.f32.f16.f16.f32 "
                            "{%0,%1,%2,%3}, {%4,%5,%6,%7}, {%8,%9}, {%0,%1,%2,%3};"
                            : "+f"(c[0]), "+f"(c[1]), "+f"(c[2]), "+f"(c[3])
                            : "r"(ra[mt][0]), "r"(ra[mt][1]), "r"(ra[mt][2]), "r"(ra[mt][3]),
                              "r"(rb[nt][h * 2]), "r"(rb[nt][h * 2 + 1]));
                    }
                }
        }
        __syncthreads();
    }

    const int g = lane >> 2, tig = lane & 3;
    #pragma unroll
    for (int mt = 0; mt < 4; mt++) {
        #pragma unroll
        for (int j = 0; j < 8; j++) {
            int row = m0 + wm * 64 + mt * 16 + g;
            int col = n0 + wn * 64 + j * 8 + tig * 2;
            float b0 = BIAS ? bias[col] : 0.f, b1 = BIAS ? bias[col + 1] : 0.f;
            float vx0 = alpha * acc[mt][j][0] + b0, vy0 = alpha * acc[mt][j][1] + b1;
            float vx1 = alpha * acc[mt][j][2] + b0, vy1 = alpha * acc[mt][j][3] + b1;
            if (OUTH) {
                __half* C = (__half*)Cv + (size_t)blockIdx.z * sC;
                *(__half2*)(C + (size_t)row * ldC + col) = __floats2half2_rn(vx0, vy0);
                *(__half2*)(C + (size_t)(row + 8) * ldC + col) = __floats2half2_rn(vx1, vy1);
            } else {
                float* C = (float*)Cv + (size_t)blockIdx.z * sC;
                float2 v0 = { vx0, vy0 }, v1 = { vx1, vy1 };
                *(float2*)(C + (size_t)row * ldC + col) = v0;
                *(float2*)(C + (size_t)(row + 8) * ldC + col) = v1;
            }
        }
    }
}

// =============== GEMM B: 128x128 tile (for P@V, N=128) =======================
#define ATILE (128*PITCH)
#define STGSZ (2*ATILE)
#define NSTG  3
#define SMEMB (NSTG*STGSZ)            // 61440

__global__ void __launch_bounds__(256, 2) gemm_h(
    const __half* __restrict__ A, const __half* __restrict__ B,
    float* __restrict__ C,
    int ldC, int K, size_t sA, size_t sB, size_t sC)
{
    extern __shared__ char smem[];
    const uint32_t sb = smem_u32(smem);
    const int tid = threadIdx.x, lane = tid & 31, wid = tid >> 5;
    const int wm = wid & 3, wn = wid >> 2;
    const int m0 = blockIdx.x * 128, n0 = blockIdx.y * 128;
    A += (size_t)blockIdx.z * sA;
    B += (size_t)blockIdx.z * sB;
    C += (size_t)blockIdx.z * sC;
    const int KT = K >> 5;

    auto load_stage = [&](int buf, int kt) {
        const int k0 = kt << 5;
        #pragma unroll
        for (int i = 0; i < 4; i++) {
            int idx = tid + (i << 8);
            int isB = idx >> 9;
            int r = (idx & 511) >> 2, ch = idx & 3;
            const __half* src = (isB ? B + (size_t)(n0 + r) * K
                                     : A + (size_t)(m0 + r) * K) + k0 + ch * 8;
            uint32_t dst = sb + buf * STGSZ + isB * ATILE + r * PITCH + ch * 16;
            asm volatile("cp.async.cg.shared.global [%0], [%1], 16;"
                         :: "r"(dst), "l"(src) : "memory");
        }
    };

    float acc[2][8][4];
    #pragma unroll
    for (int a = 0; a < 2; a++)
        #pragma unroll
        for (int b = 0; b < 8; b++)
            #pragma unroll
            for (int c = 0; c < 4; c++) acc[a][b][c] = 0.f;

    const int aRow = (lane & 7) + ((lane >> 3) & 1) * 8, aK = (lane >> 4) * 16;
    const int bRow = (lane & 7) + (lane >> 4) * 8,       bK = ((lane >> 3) & 1) * 16;
    const uint32_t aAdr0 = (uint32_t)((wm * 32 + aRow) * PITCH + aK);
    const uint32_t bAdr0 = (uint32_t)(ATILE + (wn * 64 + bRow) * PITCH + bK);

    load_stage(0, 0);
    asm volatile("cp.async.commit_group;" ::: "memory");
    if (KT > 1) load_stage(1, 1);
    asm volatile("cp.async.commit_group;" ::: "memory");

    for (int kt = 0; kt < KT; kt++) {
        asm volatile("cp.async.wait_group 1;" ::: "memory");
        __syncthreads();
        int nk = kt + 2;
        if (nk < KT) load_stage(nk % NSTG, nk);
        asm volatile("cp.async.commit_group;" ::: "memory");

        const uint32_t base = sb + (kt % NSTG) * STGSZ;
        #pragma unroll
        for (int ks = 0; ks < 2; ks++) {
            uint32_t ra[2][4], rb[4][4];
            #pragma unroll
            for (int mt = 0; mt < 2; mt++) {
                uint32_t ad = base + aAdr0 + mt * (16 * PITCH) + ks * 32;
                asm volatile("ldmatrix.sync.aligned.m8n8.x4.shared.b16 {%0,%1,%2,%3}, [%4];"
                    : "=r"(ra[mt][0]), "=r"(ra[mt][1]), "=r"(ra[mt][2]), "=r"(ra[mt][3])
                    : "r"(ad));
            }
            #pragma unroll
            for (int nt = 0; nt < 4; nt++) {
                uint32_t bd = base + bAdr0 + nt * (16 * PITCH) + ks * 32;
                asm volatile("ldmatrix.sync.aligned.m8n8.x4.shared.b16 {%0,%1,%2,%3}, [%4];"
                    : "=r"(rb[nt][0]), "=r"(rb[nt][1]), "=r"(rb[nt][2]), "=r"(rb[nt][3])
                    : "r"(bd));
            }
            #pragma unroll
            for (int mt = 0; mt < 2; mt++)
                #pragma unroll
                for (int nt = 0; nt < 4; nt++) {
                    #pragma unroll
                    for (int h = 0; h < 2; h++) {
                        float* c = acc[mt][nt * 2 + h];
                        asm volatile(
                            "mma.sync.aligned.m16n8k16.row.col.f32.f16.f16.f32 "
                            "{%0,%1,%2,%3}, {%4,%5,%6,%7}, {%8,%9}, {%0,%1,%2,%3};"
                            : "+f"(c[0]), "+f"(c[1]), "+f"(c[2]), "+f"(c[3])
                            : "r"(ra[mt][0]), "r"(ra[mt][1]), "r"(ra[mt][2]), "r"(ra[mt][3]),
                              "r"(rb[nt][h * 2]), "r"(rb[nt][h * 2 + 1]));
                    }
                }
        }
        __syncthreads();
    }

    const int g = lane >> 2, tig = lane & 3;
    #pragma unroll
    for (int mt = 0; mt < 2; mt++) {
        #pragma unroll
        for (int j = 0; j < 8; j++) {
            int row = m0 + wm * 32 + mt * 16 + g;
            int col = n0 + wn * 64 + j * 8 + tig * 2;
            float2 v0 = { acc[mt][j][0], acc[mt][j][1] };
            float2 v1 = { acc[mt][j][2], acc[mt][j][3] };
            *(float2*)(C + (size_t)row * ldC + col) = v0;
            *(float2*)(C + (size_t)(row + 8) * ldC + col) = v1;
        }
    }
}

// ---------------- elementwise ------------------------------------------------
__global__ void gemv_mod_kernel(const float* __restrict__ vec,
                                const float* __restrict__ W, const float* __restrict__ b) {
    int j = blockIdx.x * 8 + (threadIdx.x >> 5);
    int lane = threadIdx.x & 31;
    const float4* w4 = (const float4*)(W + (size_t)j * HID);
    const float4* v4 = (const float4*)vec;
    float acc = 0.f;
    for (int i = lane; i < HID/4; i += 32) {
        float4 w = w4[i], v = v4[i];
        acc += w.x * (v.x / (1.f + __expf(-v.x)));
        acc += w.y * (v.y / (1.f + __expf(-v.y)));
        acc += w.z * (v.z / (1.f + __expf(-v.z)));
        acc += w.w * (v.w / (1.f + __expf(-v.w)));
    }
    #pragma unroll
    for (int o = 16; o; o >>= 1) acc += __shfl_xor_sync(0xffffffffu, acc, o);
    if (lane == 0) g_mod[j] = acc + b[j];
}

__global__ void layernorm_kernel(const float* __restrict__ x) {
    __shared__ float shA[8], shB[8];
    __shared__ float s_mu, s_r;
    int l = blockIdx.x, t = threadIdx.x;
    const float* row = x + (size_t)l * HID;
    float v[12];
    float s = 0.f, ss = 0.f;
    #pragma unroll
    for (int i = 0; i < 12; i++) { v[i] = row[t + i*256]; s += v[i]; ss += v[i]*v[i]; }
    #pragma unroll
    for (int o = 16; o; o >>= 1) {
        s  += __shfl_xor_sync(0xffffffffu, s, o);
        ss += __shfl_xor_sync(0xffffffffu, ss, o);
    }
    if ((t & 31) == 0) { shA[t>>5] = s; shB[t>>5] = ss; }
    __syncthreads();
    if (t == 0) {
        float a = 0.f, bb = 0.f;
        #pragma unroll
        for (int w = 0; w < 8; w++) { a += shA[w]; bb += shB[w]; }
        float mu = a / HID;
        s_mu = mu; s_r = rsqrtf(bb / HID - mu*mu + EPSF);
    }
    __syncthreads();
    float mu = s_mu, r = s_r;
    __half* orow = g_a1 + (size_t)l * HID;
    #pragma unroll
    for (int i = 0; i < 12; i++) {
        int kc = t + i*256;
        float xm = (v[i] - mu) * r * (1.f + g_mod[HID + kc]) + g_mod[kc];
        orow[kc] = __float2half_rn(xm);
    }
}

__global__ void conv_w(const float* __restrict__ src, __half* __restrict__ dst, size_t n4) {
    size_t i = (size_t)blockIdx.x * blockDim.x + threadIdx.x;
    if (i >= n4) return;
    float4 v = ((const float4*)src)[i];
    ((__half2*)dst)[2*i]   = __floats2half2_rn(v.x, v.y);
    ((__half2*)dst)[2*i+1] = __floats2half2_rn(v.z, v.w);
}

__global__ void qkv_prep_kernel(const float* __restrict__ pe,
                                const float* __restrict__ q_scale,
                                const float* __restrict__ k_scale) {
    int w = threadIdx.x >> 5, lane = threadIdx.x & 31;
    int rr = blockIdx.x * 8 + w;
    int h = rr / LEN, l = rr % LEN;
    const float* prow = g_proj + (size_t)l * N1;
    float4 q4 = *(const float4*)(prow +          h*HD + lane*4);
    float4 k4 = *(const float4*)(prow + HID    + h*HD + lane*4);
    float4 v4 = *(const float4*)(prow + 2*HID  + h*HD + lane*4);
    float qs = q4.x*q4.x + q4.y*q4.y + q4.z*q4.z + q4.w*q4.w;
    float ks = k4.x*k4.x + k4.y*k4.y + k4.z*k4.z + k4.w*k4.w;
    #pragma unroll
    for (int o = 16; o; o >>= 1) {
        qs += __shfl_xor_sync(0xffffffffu, qs, o);
        ks += __shfl_xor_sync(0xffffffffu, ks, o);
    }
    float qr = rsqrtf(qs / HD + EPSF), kr = rsqrtf(ks / HD + EPSF);
    float4 qsc = *(const float4*)(q_scale + lane*4);
    float4 ksc = *(const float4*)(k_scale + lane*4);
    float tq[4] = { q4.x*qr*qsc.x, q4.y*qr*qsc.y, q4.z*qr*qsc.z, q4.w*qr*qsc.w };
    float tk[4] = { k4.x*kr*ksc.x, k4.y*kr*ksc.y, k4.z*kr*ksc.z, k4.w*kr*ksc.w };
    const float* peb = pe + (size_t)l * 256 + lane * 8;
    float oq[4], ok[4];
    oq[0] = peb[0]*tq[0] + peb[1]*tq[1];
    oq[1] = peb[2]*tq[0] + peb[3]*tq[1];
    oq[2] = peb[4]*tq[2] + peb[5]*tq[3];
    oq[3] = peb[6]*tq[2] + peb[7]*tq[3];
    ok[0] = peb[0]*tk[0] + peb[1]*tk[1];
    ok[1] = peb[2]*tk[0] + peb[3]*tk[1];
    ok[2] = peb[4]*tk[2] + peb[5]*tk[3];
    ok[3] = peb[6]*tk[2] + peb[7]*tk[3];
    size_t base = ((size_t)h * LEN + l) * HD + lane * 4;
    __half2 oqh[2] = { __floats2half2_rn(oq[0], oq[1]), __floats2half2_rn(oq[2], oq[3]) };
    __half2 okh[2] = { __floats2half2_rn(ok[0], ok[1]), __floats2half2_rn(ok[2], ok[3]) };
    *(uint2*)(g_qh + base) = *(uint2*)oqh;
    *(uint2*)(g_kh + base) = *(uint2*)okh;
    float vv[4] = { v4.x, v4.y, v4.z, v4.w };
    #pragma unroll
    for (int j = 0; j < 4; j++)
        g_vT[((size_t)h * HD + lane*4 + j) * LEN + l] = __float2half_rn(vv[j]);
}

__global__ void softmax_kernel() {
    __shared__ float shA[8];
    __shared__ float s_bc;
    size_t row = blockIdx.x;
    const __half* p = g_S + row * (size_t)LEN;
    __half* po = g_P + row * (size_t)LEN;
    int t = threadIdx.x;
    float x[12];
    float mx = -1e30f;
    #pragma unroll
    for (int i = 0; i < 12; i++) { x[i] = __half2float(p[t + i*256]); mx = fmaxf(mx, x[i]); }
    #pragma unroll
    for (int o = 16; o; o >>= 1) mx = fmaxf(mx, __shfl_xor_sync(0xffffffffu, mx, o));
    if ((t & 31) == 0) shA[t>>5] = mx;
    __syncthreads();
    if (t == 0) {
        float m = shA[0];
        #pragma unroll
        for (int w = 1; w < 8; w++) m = fmaxf(m, shA[w]);
        s_bc = m;
    }
    __syncthreads();
    mx = s_bc;
    float s = 0.f;
    #pragma unroll
    for (int i = 0; i < 12; i++) { x[i] = __expf(x[i] - mx); s += x[i]; }
    #pragma unroll
    for (int o = 16; o; o >>= 1) s += __shfl_xor_sync(0xffffffffu, s, o);
    __syncthreads();
    if ((t & 31) == 0) shA[t>>5] = s;
    __syncthreads();
    if (t == 0) {
        float a = 0.f;
        #pragma unroll
        for (int w = 0; w < 8; w++) a += shA[w];
        s_bc = 1.f / a;
    }
    __syncthreads();
    float inv = s_bc;
    #pragma unroll
    for (int i = 0; i < 12; i++) po[t + i*256] = __float2half_rn(x[i] * inv);
}

__global__ void pack_kernel() {
    size_t idx = (size_t)blockIdx.x * blockDim.x + threadIdx.x;
    if (idx >= (size_t)LEN * N2) return;
    int l = (int)(idx / N2), c = (int)(idx % N2);
    float val;
    if (c < HID) {
        val = g_attn[((size_t)(c >> 7) * LEN + l) * HD + (c & 127)];
    } else {
        float xx = g_proj[(size_t)l * N1 + 3*HID + (c - HID)];
        float inner = 0.7978845608028654f * (xx + 0.044715f * xx * xx * xx);
        val = 0.5f * xx * (1.f + tanhf(inner));
    }
    g_a2[idx] = __float2half_rn(val);
}

__global__ void final_kernel(const float* __restrict__ x, float* __restrict__ out) {
    size_t idx = (size_t)blockIdx.x * blockDim.x + threadIdx.x;
    if (idx >= (size_t)LEN * HID) return;
    int col = (int)(idx % HID);
    out[idx] = x[idx] + g_mod[2*HID + col] * out[idx];
}

// ---------------- launcher ---------------------------------------------------
extern "C" void kernel_launch(void* const* d_in, const int* in_sizes, int n_in,
                              void* d_out, int out_size) {
    const float* x       = (const float*)d_in[0];
    const float* vec     = (const float*)d_in[1];
    const float* pe      = (const float*)d_in[2];
    const float* mod_w   = (const float*)d_in[3];
    const float* mod_b   = (const float*)d_in[4];
    const float* lin1_w  = (const float*)d_in[5];
    const float* lin1_b  = (const float*)d_in[6];
    const float* lin2_w  = (const float*)d_in[7];
    const float* lin2_b  = (const float*)d_in[8];
    const float* q_scale = (const float*)d_in[9];
    const float* k_scale = (const float*)d_in[10];
    float* out = (float*)d_out;

    void *pa1, *pw1, *pa2, *pw2, *pqh, *pkh, *pvT, *pS, *pP, *pattn, *pproj;
    cudaGetSymbolAddress(&pa1, g_a1);   cudaGetSymbolAddress(&pw1, g_w1);
    cudaGetSymbolAddress(&pa2, g_a2);   cudaGetSymbolAddress(&pw2, g_w2);
    cudaGetSymbolAddress(&pqh, g_qh);   cudaGetSymbolAddress(&pkh, g_kh);
    cudaGetSymbolAddress(&pvT, g_vT);   cudaGetSymbolAddress(&pS, g_S);
    cudaGetSymbolAddress(&pP, g_P);     cudaGetSymbolAddress(&pattn, g_attn);
    cudaGetSymbolAddress(&pproj, g_proj);

    cudaFuncSetAttribute(gemm_w<false,true>, cudaFuncAttributeMaxDynamicSharedMemorySize, SMEM2);
    cudaFuncSetAttribute(gemm_w<true,false>, cudaFuncAttributeMaxDynamicSharedMemorySize, SMEM2);
    cudaFuncSetAttribute(gemm_h,             cudaFuncAttributeMaxDynamicSharedMemorySize, SMEMB);

    gemv_mod_kernel<<<(3*HID)/8, 256>>>(vec, mod_w, mod_b);              // 1
    layernorm_kernel<<<LEN, 256>>>(x);                                   // 2
    conv_w<<<(unsigned)(((size_t)N1*HID/4 + 255)/256), 256>>>(lin1_w, (__half*)pw1, (size_t)N1*HID/4); // 3

    // 4 (profiled): lin1  M=3072 N=21504 K=3072
    gemm_w<false,true><<<dim3(LEN/128, N1/256, 1), 256, SMEM2>>>(
        (const __half*)pa1, (const __half*)pw1, lin1_b, pproj,
        N1, HID, 1.f, 0, 0, 0);

    conv_w<<<(unsigned)(((size_t)HID*N2/4 + 255)/256), 256>>>(lin2_w, (__half*)pw2, (size_t)HID*N2/4); // 5
    qkv_prep_kernel<<<(NH*LEN)/8, 256>>>(pe, q_scale, k_scale);          // 6

    // 7: QK^T per head  M=3072 N=3072 K=128 -> fp16
    gemm_w<true,false><<<dim3(LEN/128, LEN/256, NH), 256, SMEM2>>>(
        (const __half*)pqh, (const __half*)pkh, nullptr, pS,
        LEN, HD, 0.08838834764831845f,
        (size_t)LEN*HD, (size_t)LEN*HD, (size_t)LEN*LEN);

    softmax_kernel<<<NH*LEN, 256>>>();                                   // 8

    // 9: P@V per head  M=3072 N=128 K=3072
    gemm_h<<<dim3(LEN/128, HD/128, NH), 256, SMEMB>>>(
        (const __half*)pP, (const __half*)pvT, (float*)pattn,
        HD, LEN,
        (size_t)LEN*LEN, (size_t)HD*LEN, (size_t)LEN*HD);

    pack_kernel<<<(unsigned)(((size_t)LEN*N2 + 255)/256), 256>>>();      // 10

    // 11: lin2  M=3072 N=3072 K=15360
    gemm_w<false,true><<<dim3(LEN/128, HID/256, 1), 256, SMEM2>>>(
        (const __half*)pa2, (const __half*)pw2, lin2_b, out,
        HID, N2, 1.f, 0, 0, 0);

    final_kernel<<<(unsigned)(((size_t)LEN*HID + 255)/256), 256>>>(x, out); // 12
}

// round 8
// speedup vs baseline: 1.1660x; 1.1660x over previous
#include <cuda_runtime.h>
#include <cuda_fp16.h>
#include <math.h>
#include <stdint.h>

#define LEN   3072
#define HID   3072
#define NH    24
#define HD    128
#define MLPD  12288
#define N1    (3*HID + MLPD)   // 21504
#define N2    (HID + MLPD)     // 15360
#define NQKV  (3*HID)          // 9216
#define EPSF  1e-6f

// ---------------- scratch ----------------------------------------------------
__device__ float g_mod[3*HID];
__device__ __align__(256) float  g_proj[(size_t)LEN*NQKV];      // qkv part only
__device__ __align__(256) __half g_a1[(size_t)LEN*HID];
__device__ __align__(256) __half g_w1[(size_t)N1*HID];
__device__ __align__(256) __half g_a2[(size_t)LEN*N2];          // [attn | gelu(mlp)]
__device__ __align__(256) __half g_w2[(size_t)HID*N2];
__device__ __align__(256) __half g_qh[(size_t)NH*LEN*HD];
__device__ __align__(256) __half g_kh[(size_t)NH*LEN*HD];
__device__ __align__(256) __half g_vT[(size_t)NH*HD*LEN];       // [h][d][l]
__device__ __align__(256) __half g_S[(size_t)NH*LEN*LEN];       // logits/probs fp16

__device__ __forceinline__ uint32_t smem_u32(const void* p) {
    uint32_t a;
    asm("{ .reg .u64 t; cvta.to.shared.u64 t, %1; cvt.u32.u64 %0, t; }" : "=r"(a) : "l"(p));
    return a;
}

// ---------------- fp16 HMMA GEMM: 128x128, BK=32, 3-stage, 2 CTA/SM ---------
#define PITCH 80
#define ATILE (128*PITCH)
#define STGSZ (2*ATILE)
#define NSTG  3
#define SMEMB (NSTG*STGSZ)            // 61440

// EPI: 0 = fp32 C + bias (lin2)
//      1 = fp16 C, *alpha, z-stride sC (QK -> S)
//      2 = fp16 -> g_a2 at col z*128 (PV)
//      3 = lin1 split: n0<9216 -> fp32+bias g_proj ; else gelu(acc+bias) -> fp16 g_a2
template<int EPI>
__global__ void __launch_bounds__(256, 2) gemm_h(
    const __half* __restrict__ A, const __half* __restrict__ B,
    const float* __restrict__ bias, void* __restrict__ Cv,
    int ldC, int K, float alpha, size_t sA, size_t sB, size_t sC)
{
    extern __shared__ char smem[];
    const uint32_t sb = smem_u32(smem);
    const int tid = threadIdx.x, lane = tid & 31, wid = tid >> 5;
    const int wm = wid & 3, wn = wid >> 2;
    const int m0 = blockIdx.x * 128, n0 = blockIdx.y * 128;
    const int z = blockIdx.z;
    A += (size_t)z * sA;
    B += (size_t)z * sB;
    const int KT = K >> 5;

    auto load_stage = [&](int buf, int kt) {
        const int k0 = kt << 5;
        #pragma unroll
        for (int i = 0; i < 4; i++) {
            int idx = tid + (i << 8);
            int isB = idx >> 9;
            int r = (idx & 511) >> 2, ch = idx & 3;
            const __half* src = (isB ? B + (size_t)(n0 + r) * K
                                     : A + (size_t)(m0 + r) * K) + k0 + ch * 8;
            uint32_t dst = sb + buf * STGSZ + isB * ATILE + r * PITCH + ch * 16;
            asm volatile("cp.async.cg.shared.global [%0], [%1], 16;"
                         :: "r"(dst), "l"(src) : "memory");
        }
    };

    float acc[2][8][4];
    #pragma unroll
    for (int a = 0; a < 2; a++)
        #pragma unroll
        for (int b = 0; b < 8; b++)
            #pragma unroll
            for (int c = 0; c < 4; c++) acc[a][b][c] = 0.f;

    const int aRow = (lane & 7) + ((lane >> 3) & 1) * 8, aK = (lane >> 4) * 16;
    const int bRow = (lane & 7) + (lane >> 4) * 8,       bK = ((lane >> 3) & 1) * 16;
    const uint32_t aAdr0 = (uint32_t)((wm * 32 + aRow) * PITCH + aK);
    const uint32_t bAdr0 = (uint32_t)(ATILE + (wn * 64 + bRow) * PITCH + bK);

    load_stage(0, 0);
    asm volatile("cp.async.commit_group;" ::: "memory");
    if (KT > 1) load_stage(1, 1);
    asm volatile("cp.async.commit_group;" ::: "memory");

    for (int kt = 0; kt < KT; kt++) {
        asm volatile("cp.async.wait_group 1;" ::: "memory");
        __syncthreads();
        int nk = kt + 2;
        if (nk < KT) load_stage(nk % NSTG, nk);
        asm volatile("cp.async.commit_group;" ::: "memory");

        const uint32_t base = sb + (kt % NSTG) * STGSZ;
        #pragma unroll
        for (int ks = 0; ks < 2; ks++) {
            uint32_t ra[2][4], rb[4][4];
            #pragma unroll
            for (int mt = 0; mt < 2; mt++) {
                uint32_t ad = base + aAdr0 + mt * (16 * PITCH) + ks * 32;
                asm volatile("ldmatrix.sync.aligned.m8n8.x4.shared.b16 {%0,%1,%2,%3}, [%4];"
                    : "=r"(ra[mt][0]), "=r"(ra[mt][1]), "=r"(ra[mt][2]), "=r"(ra[mt][3])
                    : "r"(ad));
            }
            #pragma unroll
            for (int nt = 0; nt < 4; nt++) {
                uint32_t bd = base + bAdr0 + nt * (16 * PITCH) + ks * 32;
                asm volatile("ldmatrix.sync.aligned.m8n8.x4.shared.b16 {%0,%1,%2,%3}, [%4];"
                    : "=r"(rb[nt][0]), "=r"(rb[nt][1]), "=r"(rb[nt][2]), "=r"(rb[nt][3])
                    : "r"(bd));
            }
            #pragma unroll
            for (int mt = 0; mt < 2; mt++)
                #pragma unroll
                for (int nt = 0; nt < 4; nt++) {
                    #pragma unroll
                    for (int h = 0; h < 2; h++) {
                        float* c = acc[mt][nt * 2 + h];
                        asm volatile(
                            "mma.sync.aligned.m16n8k16.row.col.f32.f16.f16.f32 "
                            "{%0,%1,%2,%3}, {%4,%5,%6,%7}, {%8,%9}, {%0,%1,%2,%3};"
                            : "+f"(c[0]), "+f"(c[1]), "+f"(c[2]), "+f"(c[3])
                            : "r"(ra[mt][0]), "r"(ra[mt][1]), "r"(ra[mt][2]), "r"(ra[mt][3]),
                              "r"(rb[nt][h * 2]), "r"(rb[nt][h * 2 + 1]));
                    }
                }
        }
        __syncthreads();
    }

    const int g = lane >> 2, tig = lane & 3;
    #pragma unroll
    for (int mt = 0; mt < 2; mt++) {
        #pragma unroll
        for (int j = 0; j < 8; j++) {
            int row = m0 + wm * 32 + mt * 16 + g;
            int col = n0 + wn * 64 + j * 8 + tig * 2;
            float v00 = acc[mt][j][0], v01 = acc[mt][j][1];
            float v10 = acc[mt][j][2], v11 = acc[mt][j][3];
            if (EPI == 0) {
                float b0 = bias[col], b1 = bias[col + 1];
                float* C = (float*)Cv;
                float2 a0 = { v00 + b0, v01 + b1 }, a1 = { v10 + b0, v11 + b1 };
                *(float2*)(C + (size_t)row * ldC + col) = a0;
                *(float2*)(C + (size_t)(row + 8) * ldC + col) = a1;
            } else if (EPI == 1) {
                __half* C = (__half*)Cv + (size_t)z * sC;
                *(__half2*)(C + (size_t)row * ldC + col) = __floats2half2_rn(alpha*v00, alpha*v01);
                *(__half2*)(C + (size_t)(row + 8) * ldC + col) = __floats2half2_rn(alpha*v10, alpha*v11);
            } else if (EPI == 2) {
                __half* C = g_a2 + (size_t)z * 128;
                *(__half2*)(C + (size_t)row * N2 + col) = __floats2half2_rn(v00, v01);
                *(__half2*)(C + (size_t)(row + 8) * N2 + col) = __floats2half2_rn(v10, v11);
            } else {  // EPI == 3 (lin1)
                float b0 = bias[col], b1 = bias[col + 1];
                v00 += b0; v01 += b1; v10 += b0; v11 += b1;
                if (n0 < NQKV) {
                    float2 a0 = { v00, v01 }, a1 = { v10, v11 };
                    *(float2*)(g_proj + (size_t)row * NQKV + col) = a0;
                    *(float2*)(g_proj + (size_t)(row + 8) * NQKV + col) = a1;
                } else {
                    auto gelu = [](float v) {
                        float inr = 0.7978845608028654f * (v + 0.044715f * v * v * v);
                        return 0.5f * v * (1.f + tanhf(inr));
                    };
                    int c2 = HID + (col - NQKV);
                    *(__half2*)(g_a2 + (size_t)row * N2 + c2) = __floats2half2_rn(gelu(v00), gelu(v01));
                    *(__half2*)(g_a2 + (size_t)(row + 8) * N2 + c2) = __floats2half2_rn(gelu(v10), gelu(v11));
                }
            }
        }
    }
}

// ---------------- elementwise ------------------------------------------------
__global__ void gemv_mod_kernel(const float* __restrict__ vec,
                                const float* __restrict__ W, const float* __restrict__ b) {
    int j = blockIdx.x * 8 + (threadIdx.x >> 5);
    int lane = threadIdx.x & 31;
    const float4* w4 = (const float4*)(W + (size_t)j * HID);
    const float4* v4 = (const float4*)vec;
    float acc = 0.f;
    for (int i = lane; i < HID/4; i += 32) {
        float4 w = w4[i], v = v4[i];
        acc += w.x * (v.x / (1.f + __expf(-v.x)));
        acc += w.y * (v.y / (1.f + __expf(-v.y)));
        acc += w.z * (v.z / (1.f + __expf(-v.z)));
        acc += w.w * (v.w / (1.f + __expf(-v.w)));
    }
    #pragma unroll
    for (int o = 16; o; o >>= 1) acc += __shfl_xor_sync(0xffffffffu, acc, o);
    if (lane == 0) g_mod[j] = acc + b[j];
}

__global__ void layernorm_kernel(const float* __restrict__ x) {
    __shared__ float shA[8], shB[8];
    __shared__ float s_mu, s_r;
    int l = blockIdx.x, t = threadIdx.x;
    const float* row = x + (size_t)l * HID;
    float v[12];
    float s = 0.f, ss = 0.f;
    #pragma unroll
    for (int i = 0; i < 12; i++) { v[i] = row[t + i*256]; s += v[i]; ss += v[i]*v[i]; }
    #pragma unroll
    for (int o = 16; o; o >>= 1) {
        s  += __shfl_xor_sync(0xffffffffu, s, o);
        ss += __shfl_xor_sync(0xffffffffu, ss, o);
    }
    if ((t & 31) == 0) { shA[t>>5] = s; shB[t>>5] = ss; }
    __syncthreads();
    if (t == 0) {
        float a = 0.f, bb = 0.f;
        #pragma unroll
        for (int w = 0; w < 8; w++) { a += shA[w]; bb += shB[w]; }
        float mu = a / HID;
        s_mu = mu; s_r = rsqrtf(bb / HID - mu*mu + EPSF);
    }
    __syncthreads();
    float mu = s_mu, r = s_r;
    __half* orow = g_a1 + (size_t)l * HID;
    #pragma unroll
    for (int i = 0; i < 12; i++) {
        int kc = t + i*256;
        float xm = (v[i] - mu) * r * (1.f + g_mod[HID + kc]) + g_mod[kc];
        orow[kc] = __float2half_rn(xm);
    }
}

__global__ void conv_w(const float4* __restrict__ src, uint2* __restrict__ dst, size_t n4) {
    size_t stride = (size_t)gridDim.x * blockDim.x;
    for (size_t i = (size_t)blockIdx.x * blockDim.x + threadIdx.x; i < n4; i += stride) {
        float4 v = src[i];
        __half2 h0 = __floats2half2_rn(v.x, v.y);
        __half2 h1 = __floats2half2_rn(v.z, v.w);
        uint2 u = { *(uint32_t*)&h0, *(uint32_t*)&h1 };
        dst[i] = u;
    }
}

// block = (h, 32 l's): q,k rms+rope; v staged in smem, written transposed
__global__ void qkv_prep_kernel(const float* __restrict__ pe,
                                const float* __restrict__ q_scale,
                                const float* __restrict__ k_scale) {
    __shared__ __half vbuf[32][136];
    int h = blockIdx.x / (LEN/32);
    int l0 = (blockIdx.x % (LEN/32)) * 32;
    int w = threadIdx.x >> 5, lane = threadIdx.x & 31;
    float4 qsc = *(const float4*)(q_scale + lane*4);
    float4 ksc = *(const float4*)(k_scale + lane*4);
    #pragma unroll
    for (int j = 0; j < 4; j++) {
        int ll = w * 4 + j;
        int l = l0 + ll;
        const float* prow = g_proj + (size_t)l * NQKV;
        float4 q4 = *(const float4*)(prow +          h*HD + lane*4);
        float4 k4 = *(const float4*)(prow + HID    + h*HD + lane*4);
        float4 v4 = *(const float4*)(prow + 2*HID  + h*HD + lane*4);
        float qs = q4.x*q4.x + q4.y*q4.y + q4.z*q4.z + q4.w*q4.w;
        float ks = k4.x*k4.x + k4.y*k4.y + k4.z*k4.z + k4.w*k4.w;
        #pragma unroll
        for (int o = 16; o; o >>= 1) {
            qs += __shfl_xor_sync(0xffffffffu, qs, o);
            ks += __shfl_xor_sync(0xffffffffu, ks, o);
        }
        float qr = rsqrtf(qs / HD + EPSF), kr = rsqrtf(ks / HD + EPSF);
        float tq[4] = { q4.x*qr*qsc.x, q4.y*qr*qsc.y, q4.z*qr*qsc.z, q4.w*qr*qsc.w };
        float tk[4] = { k4.x*kr*ksc.x, k4.y*kr*ksc.y, k4.z*kr*ksc.z, k4.w*kr*ksc.w };
        const float* peb = pe + (size_t)l * 256 + lane * 8;
        float oq[4], ok[4];
        oq[0] = peb[0]*tq[0] + peb[1]*tq[1];
        oq[1] = peb[2]*tq[0] + peb[3]*tq[1];
        oq[2] = peb[4]*tq[2] + peb[5]*tq[3];
        oq[3] = peb[6]*tq[2] + peb[7]*tq[3];
        ok[0] = peb[0]*tk[0] + peb[1]*tk[1];
        ok[1] = peb[2]*tk[0] + peb[3]*tk[1];
        ok[2] = peb[4]*tk[2] + peb[5]*tk[3];
        ok[3] = peb[6]*tk[2] + peb[7]*tk[3];
        size_t base = ((size_t)h * LEN + l) * HD + lane * 4;
        __half2 oqh[2] = { __floats2half2_rn(oq[0], oq[1]), __floats2half2_rn(oq[2], oq[3]) };
        __half2 okh[2] = { __floats2half2_rn(ok[0], ok[1]), __floats2half2_rn(ok[2], ok[3]) };
        *(uint2*)(g_qh + base) = *(uint2*)oqh;
        *(uint2*)(g_kh + base) = *(uint2*)okh;
        vbuf[ll][lane*4+0] = __float2half_rn(v4.x);
        vbuf[ll][lane*4+1] = __float2half_rn(v4.y);
        vbuf[ll][lane*4+2] = __float2half_rn(v4.z);
        vbuf[ll][lane*4+3] = __float2half_rn(v4.w);
    }
    __syncthreads();
    int d = threadIdx.x >> 1, lh = (threadIdx.x & 1) * 16;
    __align__(16) __half tmp[16];
    #pragma unroll
    for (int i = 0; i < 16; i++) tmp[i] = vbuf[lh + i][d];
    __half* dst = g_vT + ((size_t)(h * HD + d)) * LEN + l0 + lh;
    *(uint4*)dst = *(uint4*)tmp;
    *(uint4*)(dst + 8) = *(uint4*)(tmp + 8);
}

// in-place softmax over rows of g_S
__global__ void softmax_kernel() {
    __shared__ float shA[8];
    __shared__ float s_bc;
    size_t row = blockIdx.x;
    __half* p = g_S + row * (size_t)LEN;
    int t = threadIdx.x;
    float x[12];
    float mx = -1e30f;
    #pragma unroll
    for (int i = 0; i < 12; i++) { x[i] = __half2float(p[t + i*256]); mx = fmaxf(mx, x[i]); }
    #pragma unroll
    for (int o = 16; o; o >>= 1) mx = fmaxf(mx, __shfl_xor_sync(0xffffffffu, mx, o));
    if ((t & 31) == 0) shA[t>>5] = mx;
    __syncthreads();
    if (t == 0) {
        float m = shA[0];
        #pragma unroll
        for (int w = 1; w < 8; w++) m = fmaxf(m, shA[w]);
        s_bc = m;
    }
    __syncthreads();
    mx = s_bc;
    float s = 0.f;
    #pragma unroll
    for (int i = 0; i < 12; i++) { x[i] = __expf(x[i] - mx); s += x[i]; }
    #pragma unroll
    for (int o = 16; o; o >>= 1) s += __shfl_xor_sync(0xffffffffu, s, o);
    __syncthreads();
    if ((t & 31) == 0) shA[t>>5] = s;
    __syncthreads();
    if (t == 0) {
        float a = 0.f;
        #pragma unroll
        for (int w = 0; w < 8; w++) a += shA[w];
        s_bc = 1.f / a;
    }
    __syncthreads();
    float inv = s_bc;
    #pragma unroll
    for (int i = 0; i < 12; i++) p[t + i*256] = __float2half_rn(x[i] * inv);
}

__global__ void final_kernel(const float* __restrict__ x, float* __restrict__ out) {
    size_t idx = (size_t)blockIdx.x * blockDim.x + threadIdx.x;
    if (idx >= (size_t)LEN * HID) return;
    int col = (int)(idx % HID);
    out[idx] = x[idx] + g_mod[2*HID + col] * out[idx];
}

// ---------------- launcher ---------------------------------------------------
extern "C" void kernel_launch(void* const* d_in, const int* in_sizes, int n_in,
                              void* d_out, int out_size) {
    const float* x       = (const float*)d_in[0];
    const float* vec     = (const float*)d_in[1];
    const float* pe      = (const float*)d_in[2];
    const float* mod_w   = (const float*)d_in[3];
    const float* mod_b   = (const float*)d_in[4];
    const float* lin1_w  = (const float*)d_in[5];
    const float* lin1_b  = (const float*)d_in[6];
    const float* lin2_w  = (const float*)d_in[7];
    const float* lin2_b  = (const float*)d_in[8];
    const float* q_scale = (const float*)d_in[9];
    const float* k_scale = (const float*)d_in[10];
    float* out = (float*)d_out;

    void *pa1, *pw1, *pa2, *pw2, *pqh, *pkh, *pvT, *pS;
    cudaGetSymbolAddress(&pa1, g_a1);   cudaGetSymbolAddress(&pw1, g_w1);
    cudaGetSymbolAddress(&pa2, g_a2);   cudaGetSymbolAddress(&pw2, g_w2);
    cudaGetSymbolAddress(&pqh, g_qh);   cudaGetSymbolAddress(&pkh, g_kh);
    cudaGetSymbolAddress(&pvT, g_vT);   cudaGetSymbolAddress(&pS, g_S);

    cudaFuncSetAttribute(gemm_h<0>, cudaFuncAttributeMaxDynamicSharedMemorySize, SMEMB);
    cudaFuncSetAttribute(gemm_h<1>, cudaFuncAttributeMaxDynamicSharedMemorySize, SMEMB);
    cudaFuncSetAttribute(gemm_h<2>, cudaFuncAttributeMaxDynamicSharedMemorySize, SMEMB);
    cudaFuncSetAttribute(gemm_h<3>, cudaFuncAttributeMaxDynamicSharedMemorySize, SMEMB);

    gemv_mod_kernel<<<(3*HID)/8, 256>>>(vec, mod_w, mod_b);                 // 1
    layernorm_kernel<<<LEN, 256>>>(x);                                      // 2
    conv_w<<<2048, 256>>>((const float4*)lin1_w, (uint2*)pw1, (size_t)N1*HID/4); // 3

    // 4 (profiled): lin1 M=3072 N=21504 K=3072, split epilogue
    gemm_h<3><<<dim3(LEN/128, N1/128, 1), 256, SMEMB>>>(
        (const __half*)pa1, (const __half*)pw1, lin1_b, nullptr,
        0, HID, 1.f, 0, 0, 0);

    conv_w<<<2048, 256>>>((const float4*)lin2_w, (uint2*)pw2, (size_t)HID*N2/4); // 5
    qkv_prep_kernel<<<NH*(LEN/32), 256>>>(pe, q_scale, k_scale);            // 6

    // 7: QK^T per head -> g_S fp16
    gemm_h<1><<<dim3(LEN/128, LEN/128, NH), 256, SMEMB>>>(
        (const __half*)pqh, (const __half*)pkh, nullptr, pS,
        LEN, HD, 0.08838834764831845f,
        (size_t)LEN*HD, (size_t)LEN*HD, (size_t)LEN*LEN);

    softmax_kernel<<<NH*LEN, 256>>>();                                      // 8

    // 9: P@V per head -> g_a2[:, h*128 + d] fp16
    gemm_h<2><<<dim3(LEN/128, 1, NH), 256, SMEMB>>>(
        (const __half*)pS, (const __half*)pvT, nullptr, nullptr,
        0, LEN, 1.f,
        (size_t)LEN*LEN, (size_t)HD*LEN, 0);

    // 10: lin2 M=3072 N=3072 K=15360 -> d_out fp32
    gemm_h<0><<<dim3(LEN/128, HID/128, 1), 256, SMEMB>>>(
        (const __half*)pa2, (const __half*)pw2, lin2_b, out,
        HID, N2, 1.f, 0, 0, 0);

    final_kernel<<<(unsigned)(((size_t)LEN*HID + 255)/256), 256>>>(x, out); // 11
}

// round 9
// speedup vs baseline: 1.1795x; 1.0116x over previous
#include <cuda_runtime.h>
#include <cuda_fp16.h>
#include <math.h>
#include <stdint.h>

#define LEN   3072
#define HID   3072
#define NH    24
#define HD    128
#define MLPD  12288
#define N1    (3*HID + MLPD)   // 21504
#define N2    (HID + MLPD)     // 15360
#define NQKV  (3*HID)          // 9216
#define EPSF  1e-6f

// ---------------- scratch ----------------------------------------------------
__device__ float g_mod[3*HID];
__device__ __align__(256) __half g_a1[(size_t)LEN*HID];
__device__ __align__(256) __half g_w1[(size_t)N1*HID];
__device__ __align__(256) __half g_a2[(size_t)LEN*N2];          // [attn | gelu(mlp)]
__device__ __align__(256) __half g_w2[(size_t)HID*N2];
__device__ __align__(256) __half g_qh[(size_t)NH*LEN*HD];
__device__ __align__(256) __half g_kh[(size_t)NH*LEN*HD];
__device__ __align__(256) __half g_vT[(size_t)NH*HD*LEN];       // [h][d][l]
__device__ __align__(256) __half g_S[(size_t)NH*LEN*LEN];       // logits/probs fp16

__device__ __forceinline__ uint32_t smem_u32(const void* p) {
    uint32_t a;
    asm("{ .reg .u64 t; cvta.to.shared.u64 t, %1; cvt.u32.u64 %0, t; }" : "=r"(a) : "l"(p));
    return a;
}

// ---------------- fp16 HMMA GEMM: 128x128, BK=32, 3-stage, 2 CTA/SM ---------
#define PITCH 80
#define ATILE (128*PITCH)
#define STGSZ (2*ATILE)
#define NSTG  3
#define SMEMB (NSTG*STGSZ)            // 61440

// EPI: 0 = lin2: fp32 out = xres + gate*(acc+bias)
//      1 = fp16 C, *alpha, z-stride sC (QK -> S)
//      2 = fp16 -> g_a2 at col z*128 (PV)
//      3 = lin1: q/k tiles -> RMS+RoPE -> g_qh/g_kh; v tiles -> transpose -> g_vT;
//          mlp tiles -> gelu -> g_a2
template<int EPI>
__global__ void __launch_bounds__(256, 2) gemm_h(
    const __half* __restrict__ A, const __half* __restrict__ B,
    const float* __restrict__ bias, void* __restrict__ Cv,
    int ldC, int K, float alpha, size_t sA, size_t sB, size_t sC,
    const float* __restrict__ pe, const float* __restrict__ qsc,
    const float* __restrict__ ksc, const float* __restrict__ xres)
{
    extern __shared__ char smem[];
    const uint32_t sb = smem_u32(smem);
    const int tid = threadIdx.x, lane = tid & 31, wid = tid >> 5;
    const int wm = wid & 3, wn = wid >> 2;
    const int m0 = blockIdx.x * 128, n0 = blockIdx.y * 128;
    const int z = blockIdx.z;
    A += (size_t)z * sA;
    B += (size_t)z * sB;
    const int KT = K >> 5;

    auto load_stage = [&](int buf, int kt) {
        const int k0 = kt << 5;
        #pragma unroll
        for (int i = 0; i < 4; i++) {
            int idx = tid + (i << 8);
            int isB = idx >> 9;
            int r = (idx & 511) >> 2, ch = idx & 3;
            const __half* src = (isB ? B + (size_t)(n0 + r) * K
                                     : A + (size_t)(m0 + r) * K) + k0 + ch * 8;
            uint32_t dst = sb + buf * STGSZ + isB * ATILE + r * PITCH + ch * 16;
            asm volatile("cp.async.cg.shared.global [%0], [%1], 16;"
                         :: "r"(dst), "l"(src) : "memory");
        }
    };

    float acc[2][8][4];
    #pragma unroll
    for (int a = 0; a < 2; a++)
        #pragma unroll
        for (int b = 0; b < 8; b++)
            #pragma unroll
            for (int c = 0; c < 4; c++) acc[a][b][c] = 0.f;

    const int aRow = (lane & 7) + ((lane >> 3) & 1) * 8, aK = (lane >> 4) * 16;
    const int bRow = (lane & 7) + (lane >> 4) * 8,       bK = ((lane >> 3) & 1) * 16;
    const uint32_t aAdr0 = (uint32_t)((wm * 32 + aRow) * PITCH + aK);
    const uint32_t bAdr0 = (uint32_t)(ATILE + (wn * 64 + bRow) * PITCH + bK);

    load_stage(0, 0);
    asm volatile("cp.async.commit_group;" ::: "memory");
    if (KT > 1) load_stage(1, 1);
    asm volatile("cp.async.commit_group;" ::: "memory");

    for (int kt = 0; kt < KT; kt++) {
        asm volatile("cp.async.wait_group 1;" ::: "memory");
        __syncthreads();
        int nk = kt + 2;
        if (nk < KT) load_stage(nk % NSTG, nk);
        asm volatile("cp.async.commit_group;" ::: "memory");

        const uint32_t base = sb + (kt % NSTG) * STGSZ;
        #pragma unroll
        for (int ks = 0; ks < 2; ks++) {
            uint32_t ra[2][4], rb[4][4];
            #pragma unroll
            for (int mt = 0; mt < 2; mt++) {
                uint32_t ad = base + aAdr0 + mt * (16 * PITCH) + ks * 32;
                asm volatile("ldmatrix.sync.aligned.m8n8.x4.shared.b16 {%0,%1,%2,%3}, [%4];"
                    : "=r"(ra[mt][0]), "=r"(ra[mt][1]), "=r"(ra[mt][2]), "=r"(ra[mt][3])
                    : "r"(ad));
            }
            #pragma unroll
            for (int nt = 0; nt < 4; nt++) {
                uint32_t bd = base + bAdr0 + nt * (16 * PITCH) + ks * 32;
                asm volatile("ldmatrix.sync.aligned.m8n8.x4.shared.b16 {%0,%1,%2,%3}, [%4];"
                    : "=r"(rb[nt][0]), "=r"(rb[nt][1]), "=r"(rb[nt][2]), "=r"(rb[nt][3])
                    : "r"(bd));
            }
            #pragma unroll
            for (int mt = 0; mt < 2; mt++)
                #pragma unroll
                for (int nt = 0; nt < 4; nt++) {
                    #pragma unroll
                    for (int h = 0; h < 2; h++) {
                        float* c = acc[mt][nt * 2 + h];
                        asm volatile(
                            "mma.sync.aligned.m16n8k16.row.col.f32.f16.f16.f32 "
                            "{%0,%1,%2,%3}, {%4,%5,%6,%7}, {%8,%9}, {%0,%1,%2,%3};"
                            : "+f"(c[0]), "+f"(c[1]), "+f"(c[2]), "+f"(c[3])
                            : "r"(ra[mt][0]), "r"(ra[mt][1]), "r"(ra[mt][2]), "r"(ra[mt][3]),
                              "r"(rb[nt][h * 2]), "r"(rb[nt][h * 2 + 1]));
                    }
                }
        }
        __syncthreads();
    }

    const int g = lane >> 2, tig = lane & 3;

    if (EPI == 3 && n0 < NQKV) {
        // drain cp.async, free smem for reuse
        asm volatile("cp.async.wait_group 0;" ::: "memory");
        __syncthreads();
        if (n0 < 2 * HID) {
            // ---- q or k tile: bias + RMS + RoPE + fp16 store ----
            const bool isq = (n0 < HID);
            const int h = (n0 - (isq ? 0 : HID)) >> 7;
            const float* sc = isq ? qsc : ksc;
            __half* dbuf = isq ? g_qh : g_kh;
            float* rsum = (float*)smem;                       // [128][2]
            float ss[2][2] = {{0.f, 0.f}, {0.f, 0.f}};
            #pragma unroll
            for (int mt = 0; mt < 2; mt++)
                #pragma unroll
                for (int j = 0; j < 8; j++) {
                    int col = wn * 64 + j * 8 + tig * 2;
                    float b0 = bias[n0 + col], b1 = bias[n0 + col + 1];
                    float t00 = acc[mt][j][0] + b0, t01 = acc[mt][j][1] + b1;
                    float t10 = acc[mt][j][2] + b0, t11 = acc[mt][j][3] + b1;
                    ss[mt][0] += t00 * t00 + t01 * t01;
                    ss[mt][1] += t10 * t10 + t11 * t11;
                }
            #pragma unroll
            for (int mt = 0; mt < 2; mt++)
                #pragma unroll
                for (int hh = 0; hh < 2; hh++) {
                    float v = ss[mt][hh];
                    v += __shfl_xor_sync(0xffffffffu, v, 1);
                    v += __shfl_xor_sync(0xffffffffu, v, 2);
                    if (tig == 0) rsum[(wm * 32 + mt * 16 + g + hh * 8) * 2 + wn] = v;
                }
            __syncthreads();
            float rr[2][2];
            #pragma unroll
            for (int mt = 0; mt < 2; mt++)
                #pragma unroll
                for (int hh = 0; hh < 2; hh++) {
                    int lr = wm * 32 + mt * 16 + g + hh * 8;
                    rr[mt][hh] = rsqrtf((rsum[lr * 2] + rsum[lr * 2 + 1]) * (1.f / HD) + EPSF);
                }
            #pragma unroll
            for (int mt = 0; mt < 2; mt++)
                #pragma unroll
                for (int j = 0; j < 8; j++) {
                    int d = wn * 64 + j * 8 + tig * 2;
                    float b0 = bias[n0 + d], b1 = bias[n0 + d + 1];
                    float s0 = sc[d], s1 = sc[d + 1];
                    #pragma unroll
                    for (int hh = 0; hh < 2; hh++) {
                        int lr = wm * 32 + mt * 16 + g + hh * 8;
                        int l = m0 + lr;
                        float t0 = (acc[mt][j][hh * 2]     + b0) * rr[mt][hh] * s0;
                        float t1 = (acc[mt][j][hh * 2 + 1] + b1) * rr[mt][hh] * s1;
                        float4 p = *(const float4*)(pe + (size_t)l * 256 + d * 2);
                        float o0 = p.x * t0 + p.y * t1;
                        float o1 = p.z * t0 + p.w * t1;
                        *(__half2*)(dbuf + ((size_t)h * LEN + l) * HD + d) =
                            __floats2half2_rn(o0, o1);
                    }
                }
        } else {
            // ---- v tile: bias + fp16, smem transpose -> g_vT ----
            const int h = (n0 - 2 * HID) >> 7;
            __half* vs = (__half*)smem;                       // [128][136]
            #pragma unroll
            for (int mt = 0; mt < 2; mt++)
                #pragma unroll
                for (int j = 0; j < 8; j++) {
                    int d = wn * 64 + j * 8 + tig * 2;
                    float b0 = bias[n0 + d], b1 = bias[n0 + d + 1];
                    #pragma unroll
                    for (int hh = 0; hh < 2; hh++) {
                        int lr = wm * 32 + mt * 16 + g + hh * 8;
                        *(__half2*)(vs + lr * 136 + d) =
                            __floats2half2_rn(acc[mt][j][hh * 2] + b0,
                                              acc[mt][j][hh * 2 + 1] + b1);
                    }
                }
            __syncthreads();
            int d = tid >> 1, lh = (tid & 1) * 64;
            __align__(16) __half tmp[64];
            #pragma unroll
            for (int i = 0; i < 64; i++) tmp[i] = vs[(lh + i) * 136 + d];
            __half* dst = g_vT + ((size_t)h * HD + d) * LEN + m0 + lh;
            #pragma unroll
            for (int i = 0; i < 8; i++)
                *(uint4*)(dst + i * 8) = *(uint4*)(tmp + i * 8);
        }
        return;
    }

    #pragma unroll
    for (int mt = 0; mt < 2; mt++) {
        #pragma unroll
        for (int j = 0; j < 8; j++) {
            int row = m0 + wm * 32 + mt * 16 + g;
            int col = n0 + wn * 64 + j * 8 + tig * 2;
            float v00 = acc[mt][j][0], v01 = acc[mt][j][1];
            float v10 = acc[mt][j][2], v11 = acc[mt][j][3];
            if (EPI == 0) {
                float b0 = bias[col], b1 = bias[col + 1];
                float g0 = g_mod[2 * HID + col], g1 = g_mod[2 * HID + col + 1];
                float* C = (float*)Cv;
                float2 x0 = *(const float2*)(xres + (size_t)row * HID + col);
                float2 x1 = *(const float2*)(xres + (size_t)(row + 8) * HID + col);
                float2 a0 = { x0.x + g0 * (v00 + b0), x0.y + g1 * (v01 + b1) };
                float2 a1 = { x1.x + g0 * (v10 + b0), x1.y + g1 * (v11 + b1) };
                *(float2*)(C + (size_t)row * ldC + col) = a0;
                *(float2*)(C + (size_t)(row + 8) * ldC + col) = a1;
            } else if (EPI == 1) {
                __half* C = (__half*)Cv + (size_t)z * sC;
                *(__half2*)(C + (size_t)row * ldC + col) = __floats2half2_rn(alpha*v00, alpha*v01);
                *(__half2*)(C + (size_t)(row + 8) * ldC + col) = __floats2half2_rn(alpha*v10, alpha*v11);
            } else if (EPI == 2) {
                __half* C = g_a2 + (size_t)z * 128;
                *(__half2*)(C + (size_t)row * N2 + col) = __floats2half2_rn(v00, v01);
                *(__half2*)(C + (size_t)(row + 8) * N2 + col) = __floats2half2_rn(v10, v11);
            } else {  // EPI == 3, mlp tile
                float b0 = bias[col], b1 = bias[col + 1];
                v00 += b0; v01 += b1; v10 += b0; v11 += b1;
                auto gelu = [](float v) {
                    float inr = 0.7978845608028654f * (v + 0.044715f * v * v * v);
                    return 0.5f * v * (1.f + tanhf(inr));
                };
                int c2 = HID + (col - NQKV);
                *(__half2*)(g_a2 + (size_t)row * N2 + c2) = __floats2half2_rn(gelu(v00), gelu(v01));
                *(__half2*)(g_a2 + (size_t)(row + 8) * N2 + c2) = __floats2half2_rn(gelu(v10), gelu(v11));
            }
        }
    }
}

// ---------------- elementwise ------------------------------------------------
__global__ void gemv_mod_kernel(const float* __restrict__ vec,
                                const float* __restrict__ W, const float* __restrict__ b) {
    int j = blockIdx.x * 8 + (threadIdx.x >> 5);
    int lane = threadIdx.x & 31;
    const float4* w4 = (const float4*)(W + (size_t)j * HID);
    const float4* v4 = (const float4*)vec;
    float acc = 0.f;
    for (int i = lane; i < HID/4; i += 32) {
        float4 w = w4[i], v = v4[i];
        acc += w.x * (v.x / (1.f + __expf(-v.x)));
        acc += w.y * (v.y / (1.f + __expf(-v.y)));
        acc += w.z * (v.z / (1.f + __expf(-v.z)));
        acc += w.w * (v.w / (1.f + __expf(-v.w)));
    }
    #pragma unroll
    for (int o = 16; o; o >>= 1) acc += __shfl_xor_sync(0xffffffffu, acc, o);
    if (lane == 0) g_mod[j] = acc + b[j];
}

__global__ void layernorm_kernel(const float* __restrict__ x) {
    __shared__ float shA[8], shB[8];
    __shared__ float s_mu, s_r;
    int l = blockIdx.x, t = threadIdx.x;
    const float* row = x + (size_t)l * HID;
    float v[12];
    float s = 0.f, ss = 0.f;
    #pragma unroll
    for (int i = 0; i < 12; i++) { v[i] = row[t + i*256]; s += v[i]; ss += v[i]*v[i]; }
    #pragma unroll
    for (int o = 16; o; o >>= 1) {
        s  += __shfl_xor_sync(0xffffffffu, s, o);
        ss += __shfl_xor_sync(0xffffffffu, ss, o);
    }
    if ((t & 31) == 0) { shA[t>>5] = s; shB[t>>5] = ss; }
    __syncthreads();
    if (t == 0) {
        float a = 0.f, bb = 0.f;
        #pragma unroll
        for (int w = 0; w < 8; w++) { a += shA[w]; bb += shB[w]; }
        float mu = a / HID;
        s_mu = mu; s_r = rsqrtf(bb / HID - mu*mu + EPSF);
    }
    __syncthreads();
    float mu = s_mu, r = s_r;
    __half* orow = g_a1 + (size_t)l * HID;
    #pragma unroll
    for (int i = 0; i < 12; i++) {
        int kc = t + i*256;
        float xm = (v[i] - mu) * r * (1.f + g_mod[HID + kc]) + g_mod[kc];
        orow[kc] = __float2half_rn(xm);
    }
}

__global__ void conv_w(const float4* __restrict__ src, uint2* __restrict__ dst, size_t n4) {
    size_t stride = (size_t)gridDim.x * blockDim.x;
    for (size_t i = (size_t)blockIdx.x * blockDim.x + threadIdx.x; i < n4; i += stride) {
        float4 v = src[i];
        __half2 h0 = __floats2half2_rn(v.x, v.y);
        __half2 h1 = __floats2half2_rn(v.z, v.w);
        uint2 u = { *(uint32_t*)&h0, *(uint32_t*)&h1 };
        dst[i] = u;
    }
}

// in-place softmax over rows of g_S
__global__ void softmax_kernel() {
    __shared__ float shA[8];
    __shared__ float s_bc;
    size_t row = blockIdx.x;
    __half* p = g_S + row * (size_t)LEN;
    int t = threadIdx.x;
    float x[12];
    float mx = -1e30f;
    #pragma unroll
    for (int i = 0; i < 12; i++) { x[i] = __half2float(p[t + i*256]); mx = fmaxf(mx, x[i]); }
    #pragma unroll
    for (int o = 16; o; o >>= 1) mx = fmaxf(mx, __shfl_xor_sync(0xffffffffu, mx, o));
    if ((t & 31) == 0) shA[t>>5] = mx;
    __syncthreads();
    if (t == 0) {
        float m = shA[0];
        #pragma unroll
        for (int w = 1; w < 8; w++) m = fmaxf(m, shA[w]);
        s_bc = m;
    }
    __syncthreads();
    mx = s_bc;
    float s = 0.f;
    #pragma unroll
    for (int i = 0; i < 12; i++) { x[i] = __expf(x[i] - mx); s += x[i]; }
    #pragma unroll
    for (int o = 16; o; o >>= 1) s += __shfl_xor_sync(0xffffffffu, s, o);
    __syncthreads();
    if ((t & 31) == 0) shA[t>>5] = s;
    __syncthreads();
    if (t == 0) {
        float a = 0.f;
        #pragma unroll
        for (int w = 0; w < 8; w++) a += shA[w];
        s_bc = 1.f / a;
    }
    __syncthreads();
    float inv = s_bc;
    #pragma unroll
    for (int i = 0; i < 12; i++) p[t + i*256] = __float2half_rn(x[i] * inv);
}

// ---------------- launcher ---------------------------------------------------
extern "C" void kernel_launch(void* const* d_in, const int* in_sizes, int n_in,
                              void* d_out, int out_size) {
    const float* x       = (const float*)d_in[0];
    const float* vec     = (const float*)d_in[1];
    const float* pe      = (const float*)d_in[2];
    const float* mod_w   = (const float*)d_in[3];
    const float* mod_b   = (const float*)d_in[4];
    const float* lin1_w  = (const float*)d_in[5];
    const float* lin1_b  = (const float*)d_in[6];
    const float* lin2_w  = (const float*)d_in[7];
    const float* lin2_b  = (const float*)d_in[8];
    const float* q_scale = (const float*)d_in[9];
    const float* k_scale = (const float*)d_in[10];
    float* out = (float*)d_out;

    void *pa1, *pw1, *pa2, *pw2, *pqh, *pkh, *pvT, *pS;
    cudaGetSymbolAddress(&pa1, g_a1);   cudaGetSymbolAddress(&pw1, g_w1);
    cudaGetSymbolAddress(&pa2, g_a2);   cudaGetSymbolAddress(&pw2, g_w2);
    cudaGetSymbolAddress(&pqh, g_qh);   cudaGetSymbolAddress(&pkh, g_kh);
    cudaGetSymbolAddress(&pvT, g_vT);   cudaGetSymbolAddress(&pS, g_S);

    cudaFuncSetAttribute(gemm_h<0>, cudaFuncAttributeMaxDynamicSharedMemorySize, SMEMB);
    cudaFuncSetAttribute(gemm_h<1>, cudaFuncAttributeMaxDynamicSharedMemorySize, SMEMB);
    cudaFuncSetAttribute(gemm_h<2>, cudaFuncAttributeMaxDynamicSharedMemorySize, SMEMB);
    cudaFuncSetAttribute(gemm_h<3>, cudaFuncAttributeMaxDynamicSharedMemorySize, SMEMB);

    gemv_mod_kernel<<<(3*HID)/8, 256>>>(vec, mod_w, mod_b);                 // 1
    layernorm_kernel<<<LEN, 256>>>(x);                                      // 2
    conv_w<<<2048, 256>>>((const float4*)lin1_w, (uint2*)pw1, (size_t)N1*HID/4); // 3

    // 4 (profiled): lin1 M=3072 N=21504 K=3072; epilogue does RMS/RoPE/vT/gelu
    gemm_h<3><<<dim3(LEN/128, N1/128, 1), 256, SMEMB>>>(
        (const __half*)pa1, (const __half*)pw1, lin1_b, nullptr,
        0, HID, 1.f, 0, 0, 0, pe, q_scale, k_scale, nullptr);

    conv_w<<<2048, 256>>>((const float4*)lin2_w, (uint2*)pw2, (size_t)HID*N2/4); // 5

    // 6: QK^T per head -> g_S fp16
    gemm_h<1><<<dim3(LEN/128, LEN/128, NH), 256, SMEMB>>>(
        (const __half*)pqh, (const __half*)pkh, nullptr, pS,
        LEN, HD, 0.08838834764831845f,
        (size_t)LEN*HD, (size_t)LEN*HD, (size_t)LEN*LEN,
        nullptr, nullptr, nullptr, nullptr);

    softmax_kernel<<<NH*LEN, 256>>>();                                      // 7

    // 8: P@V per head -> g_a2[:, h*128 + d] fp16
    gemm_h<2><<<dim3(LEN/128, 1, NH), 256, SMEMB>>>(
        (const __half*)pS, (const __half*)pvT, nullptr, nullptr,
        0, LEN, 1.f,
        (size_t)LEN*LEN, (size_t)HD*LEN, 0,
        nullptr, nullptr, nullptr, nullptr);

    // 9: lin2 M=3072 N=3072 K=15360 -> out = x + gate*(acc+bias)
    gemm_h<0><<<dim3(LEN/128, HID/128, 1), 256, SMEMB>>>(
        (const __half*)pa2, (const __half*)pw2, lin2_b, out,
        HID, N2, 1.f, 0, 0, 0,
        nullptr, nullptr, nullptr, x);
}

// round 10
// speedup vs baseline: 1.3020x; 1.1038x over previous
#include <cuda_runtime.h>
#include <cuda_fp16.h>
#include <math.h>
#include <stdint.h>

#define LEN   3072
#define HID   3072
#define NH    24
#define HD    128
#define MLPD  12288
#define N1    (3*HID + MLPD)   // 21504
#define N2    (HID + MLPD)     // 15360
#define NQKV  (3*HID)          // 9216
#define EPSF  1e-6f

// ---------------- scratch ----------------------------------------------------
__device__ float g_mod[3*HID];
__device__ __align__(256) __half g_a1[(size_t)LEN*HID];
__device__ __align__(256) __half g_w1[(size_t)N1*HID];
__device__ __align__(256) __half g_a2[(size_t)LEN*N2];          // [attn | gelu(mlp)]
__device__ __align__(256) __half g_w2[(size_t)HID*N2];
__device__ __align__(256) __half g_qh[(size_t)NH*LEN*HD];
__device__ __align__(256) __half g_kh[(size_t)NH*LEN*HD];
__device__ __align__(256) __half g_vT[(size_t)NH*HD*LEN];       // [h][d][l]

__device__ __forceinline__ uint32_t smem_u32(const void* p) {
    uint32_t a;
    asm("{ .reg .u64 t; cvta.to.shared.u64 t, %1; cvt.u32.u64 %0, t; }" : "=r"(a) : "l"(p));
    return a;
}

// ---------------- fp16 HMMA GEMM: 128x128, BK=32, 3-stage, 2 CTA/SM ---------
#define PITCH 80
#define ATILE (128*PITCH)
#define STGSZ (2*ATILE)
#define NSTG  3
#define SMEMB (NSTG*STGSZ)            // 61440

// EPI: 0 = lin2: fp32 out = xres + gate*(acc+bias)
//      3 = lin1: q/k tiles -> RMS+RoPE -> g_qh/g_kh; v tiles -> transpose -> g_vT;
//          mlp tiles -> gelu -> g_a2
template<int EPI>
__global__ void __launch_bounds__(256, 2) gemm_h(
    const __half* __restrict__ A, const __half* __restrict__ B,
    const float* __restrict__ bias, void* __restrict__ Cv,
    int ldC, int K,
    const float* __restrict__ pe, const float* __restrict__ qsc,
    const float* __restrict__ ksc, const float* __restrict__ xres)
{
    extern __shared__ char smem[];
    const uint32_t sb = smem_u32(smem);
    const int tid = threadIdx.x, lane = tid & 31, wid = tid >> 5;
    const int wm = wid & 3, wn = wid >> 2;
    const int m0 = blockIdx.x * 128, n0 = blockIdx.y * 128;
    const int KT = K >> 5;

    auto load_stage = [&](int buf, int kt) {
        const int k0 = kt << 5;
        #pragma unroll
        for (int i = 0; i < 4; i++) {
            int idx = tid + (i << 8);
            int isB = idx >> 9;
            int r = (idx & 511) >> 2, ch = idx & 3;
            const __half* src = (isB ? B + (size_t)(n0 + r) * K
                                     : A + (size_t)(m0 + r) * K) + k0 + ch * 8;
            uint32_t dst = sb + buf * STGSZ + isB * ATILE + r * PITCH + ch * 16;
            asm volatile("cp.async.cg.shared.global [%0], [%1], 16;"
                         :: "r"(dst), "l"(src) : "memory");
        }
    };

    float acc[2][8][4];
    #pragma unroll
    for (int a = 0; a < 2; a++)
        #pragma unroll
        for (int b = 0; b < 8; b++)
            #pragma unroll
            for (int c = 0; c < 4; c++) acc[a][b][c] = 0.f;

    const int aRow = (lane & 7) + ((lane >> 3) & 1) * 8, aK = (lane >> 4) * 16;
    const int bRow = (lane & 7) + (lane >> 4) * 8,       bK = ((lane >> 3) & 1) * 16;
    const uint32_t aAdr0 = (uint32_t)((wm * 32 + aRow) * PITCH + aK);
    const uint32_t bAdr0 = (uint32_t)(ATILE + (wn * 64 + bRow) * PITCH + bK);

    load_stage(0, 0);
    asm volatile("cp.async.commit_group;" ::: "memory");
    if (KT > 1) load_stage(1, 1);
    asm volatile("cp.async.commit_group;" ::: "memory");

    for (int kt = 0; kt < KT; kt++) {
        asm volatile("cp.async.wait_group 1;" ::: "memory");
        __syncthreads();
        int nk = kt + 2;
        if (nk < KT) load_stage(nk % NSTG, nk);
        asm volatile("cp.async.commit_group;" ::: "memory");

        const uint32_t base = sb + (kt % NSTG) * STGSZ;
        #pragma unroll
        for (int ks = 0; ks < 2; ks++) {
            uint32_t ra[2][4], rb[4][4];
            #pragma unroll
            for (int mt = 0; mt < 2; mt++) {
                uint32_t ad = base + aAdr0 + mt * (16 * PITCH) + ks * 32;
                asm volatile("ldmatrix.sync.aligned.m8n8.x4.shared.b16 {%0,%1,%2,%3}, [%4];"
                    : "=r"(ra[mt][0]), "=r"(ra[mt][1]), "=r"(ra[mt][2]), "=r"(ra[mt][3])
                    : "r"(ad));
            }
            #pragma unroll
            for (int nt = 0; nt < 4; nt++) {
                uint32_t bd = base + bAdr0 + nt * (16 * PITCH) + ks * 32;
                asm volatile("ldmatrix.sync.aligned.m8n8.x4.shared.b16 {%0,%1,%2,%3}, [%4];"
                    : "=r"(rb[nt][0]), "=r"(rb[nt][1]), "=r"(rb[nt][2]), "=r"(rb[nt][3])
                    : "r"(bd));
            }
            #pragma unroll
            for (int mt = 0; mt < 2; mt++)
                #pragma unroll
                for (int nt = 0; nt < 4; nt++) {
                    #pragma unroll
                    for (int h = 0; h < 2; h++) {
                        float* c = acc[mt][nt * 2 + h];
                        asm volatile(
                            "mma.sync.aligned.m16n8k16.row.col.f32.f16.f16.f32 "
                            "{%0,%1,%2,%3}, {%4,%5,%6,%7}, {%8,%9}, {%0,%1,%2,%3};"
                            : "+f"(c[0]), "+f"(c[1]), "+f"(c[2]), "+f"(c[3])
                            : "r"(ra[mt][0]), "r"(ra[mt][1]), "r"(ra[mt][2]), "r"(ra[mt][3]),
                              "r"(rb[nt][h * 2]), "r"(rb[nt][h * 2 + 1]));
                    }
                }
        }
        __syncthreads();
    }

    const int g = lane >> 2, tig = lane & 3;

    if (EPI == 3 && n0 < NQKV) {
        asm volatile("cp.async.wait_group 0;" ::: "memory");
        __syncthreads();
        if (n0 < 2 * HID) {
            const bool isq = (n0 < HID);
            const int h = (n0 - (isq ? 0 : HID)) >> 7;
            const float* sc = isq ? qsc : ksc;
            __half* dbuf = isq ? g_qh : g_kh;
            float* rsum = (float*)smem;
            float ss[2][2] = {{0.f, 0.f}, {0.f, 0.f}};
            #pragma unroll
            for (int mt = 0; mt < 2; mt++)
                #pragma unroll
                for (int j = 0; j < 8; j++) {
                    int col = wn * 64 + j * 8 + tig * 2;
                    float b0 = bias[n0 + col], b1 = bias[n0 + col + 1];
                    float t00 = acc[mt][j][0] + b0, t01 = acc[mt][j][1] + b1;
                    float t10 = acc[mt][j][2] + b0, t11 = acc[mt][j][3] + b1;
                    ss[mt][0] += t00 * t00 + t01 * t01;
                    ss[mt][1] += t10 * t10 + t11 * t11;
                }
            #pragma unroll
            for (int mt = 0; mt < 2; mt++)
                #pragma unroll
                for (int hh = 0; hh < 2; hh++) {
                    float v = ss[mt][hh];
                    v += __shfl_xor_sync(0xffffffffu, v, 1);
                    v += __shfl_xor_sync(0xffffffffu, v, 2);
                    if (tig == 0) rsum[(wm * 32 + mt * 16 + g + hh * 8) * 2 + wn] = v;
                }
            __syncthreads();
            float rr[2][2];
            #pragma unroll
            for (int mt = 0; mt < 2; mt++)
                #pragma unroll
                for (int hh = 0; hh < 2; hh++) {
                    int lr = wm * 32 + mt * 16 + g + hh * 8;
                    rr[mt][hh] = rsqrtf((rsum[lr * 2] + rsum[lr * 2 + 1]) * (1.f / HD) + EPSF);
                }
            #pragma unroll
            for (int mt = 0; mt < 2; mt++)
                #pragma unroll
                for (int j = 0; j < 8; j++) {
                    int d = wn * 64 + j * 8 + tig * 2;
                    float b0 = bias[n0 + d], b1 = bias[n0 + d + 1];
                    float s0 = sc[d], s1 = sc[d + 1];
                    #pragma unroll
                    for (int hh = 0; hh < 2; hh++) {
                        int lr = wm * 32 + mt * 16 + g + hh * 8;
                        int l = m0 + lr;
                        float t0 = (acc[mt][j][hh * 2]     + b0) * rr[mt][hh] * s0;
                        float t1 = (acc[mt][j][hh * 2 + 1] + b1) * rr[mt][hh] * s1;
                        float4 p = *(const float4*)(pe + (size_t)l * 256 + d * 2);
                        float o0 = p.x * t0 + p.y * t1;
                        float o1 = p.z * t0 + p.w * t1;
                        *(__half2*)(dbuf + ((size_t)h * LEN + l) * HD + d) =
                            __floats2half2_rn(o0, o1);
                    }
                }
        } else {
            const int h = (n0 - 2 * HID) >> 7;
            __half* vs = (__half*)smem;
            #pragma unroll
            for (int mt = 0; mt < 2; mt++)
                #pragma unroll
                for (int j = 0; j < 8; j++) {
                    int d = wn * 64 + j * 8 + tig * 2;
                    float b0 = bias[n0 + d], b1 = bias[n0 + d + 1];
                    #pragma unroll
                    for (int hh = 0; hh < 2; hh++) {
                        int lr = wm * 32 + mt * 16 + g + hh * 8;
                        *(__half2*)(vs + lr * 136 + d) =
                            __floats2half2_rn(acc[mt][j][hh * 2] + b0,
                                              acc[mt][j][hh * 2 + 1] + b1);
                    }
                }
            __syncthreads();
            int d = tid >> 1, lh = (tid & 1) * 64;
            __align__(16) __half tmp[64];
            #pragma unroll
            for (int i = 0; i < 64; i++) tmp[i] = vs[(lh + i) * 136 + d];
            __half* dst = g_vT + ((size_t)h * HD + d) * LEN + m0 + lh;
            #pragma unroll
            for (int i = 0; i < 8; i++)
                *(uint4*)(dst + i * 8) = *(uint4*)(tmp + i * 8);
        }
        return;
    }

    #pragma unroll
    for (int mt = 0; mt < 2; mt++) {
        #pragma unroll
        for (int j = 0; j < 8; j++) {
            int row = m0 + wm * 32 + mt * 16 + g;
            int col = n0 + wn * 64 + j * 8 + tig * 2;
            float v00 = acc[mt][j][0], v01 = acc[mt][j][1];
            float v10 = acc[mt][j][2], v11 = acc[mt][j][3];
            if (EPI == 0) {
                float b0 = bias[col], b1 = bias[col + 1];
                float g0 = g_mod[2 * HID + col], g1 = g_mod[2 * HID + col + 1];
                float* C = (float*)Cv;
                float2 x0 = *(const float2*)(xres + (size_t)row * HID + col);
                float2 x1 = *(const float2*)(xres + (size_t)(row + 8) * HID + col);
                float2 a0 = { x0.x + g0 * (v00 + b0), x0.y + g1 * (v01 + b1) };
                float2 a1 = { x1.x + g0 * (v10 + b0), x1.y + g1 * (v11 + b1) };
                *(float2*)(C + (size_t)row * ldC + col) = a0;
                *(float2*)(C + (size_t)(row + 8) * ldC + col) = a1;
            } else {  // EPI == 3, mlp tile
                float b0 = bias[col], b1 = bias[col + 1];
                v00 += b0; v01 += b1; v10 += b0; v11 += b1;
                auto gelu = [](float v) {
                    float inr = 0.7978845608028654f * (v + 0.044715f * v * v * v);
                    return 0.5f * v * (1.f + tanhf(inr));
                };
                int c2 = HID + (col - NQKV);
                *(__half2*)(g_a2 + (size_t)row * N2 + c2) = __floats2half2_rn(gelu(v00), gelu(v01));
                *(__half2*)(g_a2 + (size_t)(row + 8) * N2 + c2) = __floats2half2_rn(gelu(v10), gelu(v11));
            }
        }
    }
}

// ---------------- flash attention --------------------------------------------
// CTA = (q-tile 128, head). 8 warps x 16 q rows. Q resident; K/V double-buffered.
// smem: Q 40960 | buf0 K 40960 V 40960 | buf1 K 40960 V 40960  = 204800 B
#define FA_Q    0
#define FA_KV   40960
#define FA_KVSZ 81920
#define FA_SMEM 204800
#define NKT     (LEN/128)      // 24

__global__ void __launch_bounds__(256, 1) flash_attn() {
    extern __shared__ char smem[];
    const uint32_t sb = smem_u32(smem);
    const int tid = threadIdx.x, lane = tid & 31, wid = tid >> 5;
    const int g = lane >> 2, tig = lane & 3;
    const int m0 = blockIdx.x * 128;
    const int h = blockIdx.y;
    const float alpha = 0.08838834764831845f;

    // ---- prologue: Q + K0 + V0 (group 0) ----
    #pragma unroll
    for (int i = 0; i < 8; i++) {
        int q = tid + (i << 8);
        int r = q >> 4, c = q & 15;
        const __half* src = g_qh + ((size_t)h * LEN + m0 + r) * HD + c * 8;
        uint32_t dst = sb + FA_Q + (c >> 2) * 10240 + r * 80 + (c & 3) * 16;
        asm volatile("cp.async.cg.shared.global [%0], [%1], 16;" :: "r"(dst), "l"(src) : "memory");
    }
    auto load_kv = [&](int j, int buf) {
        #pragma unroll
        for (int i = 0; i < 16; i++) {
            int idx = tid + (i << 8);
            int isV = idx >> 11;
            int e = idx & 2047;
            int r = e >> 4, c = e & 15;
            const __half* src = isV
                ? g_vT + ((size_t)h * HD + r) * LEN + j * 128 + c * 8
                : g_kh + ((size_t)h * LEN + j * 128 + r) * HD + c * 8;
            uint32_t dst = sb + FA_KV + buf * FA_KVSZ + isV * 40960
                         + (c >> 2) * 10240 + r * 80 + (c & 3) * 16;
            asm volatile("cp.async.cg.shared.global [%0], [%1], 16;" :: "r"(dst), "l"(src) : "memory");
        }
    };
    load_kv(0, 0);
    asm volatile("cp.async.commit_group;" ::: "memory");

    float o[16][4];
    #pragma unroll
    for (int a = 0; a < 16; a++)
        #pragma unroll
        for (int b = 0; b < 4; b++) o[a][b] = 0.f;
    float mrow[2] = { -1e30f, -1e30f };
    float lrow[2] = { 0.f, 0.f };

    const int aRow = (lane & 7) + ((lane >> 3) & 1) * 8, aK = (lane >> 4) * 16;
    const int bRow = (lane & 7) + (lane >> 4) * 8,       bK = ((lane >> 3) & 1) * 16;
    const uint32_t qAdr = (uint32_t)((wid * 16 + aRow) * 80 + aK);

    for (int j = 0; j < NKT; j++) {
        __syncthreads();
        if (j + 1 < NKT) load_kv(j + 1, (j + 1) & 1);
        asm volatile("cp.async.commit_group;" ::: "memory");
        asm volatile("cp.async.wait_group 1;" ::: "memory");
        __syncthreads();

        const uint32_t kb = sb + FA_KV + (j & 1) * FA_KVSZ;
        const uint32_t vb = kb + 40960;

        // ---- S = Q @ K^T ----
        float s[16][4];
        #pragma unroll
        for (int a = 0; a < 16; a++)
            #pragma unroll
            for (int b = 0; b < 4; b++) s[a][b] = 0.f;
        #pragma unroll
        for (int kc = 0; kc < 4; kc++) {
            #pragma unroll
            for (int ks = 0; ks < 2; ks++) {
                uint32_t ra[4], rb[8][4];
                uint32_t ad = sb + FA_Q + kc * 10240 + qAdr + ks * 32;
                asm volatile("ldmatrix.sync.aligned.m8n8.x4.shared.b16 {%0,%1,%2,%3}, [%4];"
                    : "=r"(ra[0]), "=r"(ra[1]), "=r"(ra[2]), "=r"(ra[3]) : "r"(ad));
                #pragma unroll
                for (int bp = 0; bp < 8; bp++) {
                    uint32_t bd = kb + kc * 10240 + (bp * 16 + bRow) * 80 + ks * 32 + bK;
                    asm volatile("ldmatrix.sync.aligned.m8n8.x4.shared.b16 {%0,%1,%2,%3}, [%4];"
                        : "=r"(rb[bp][0]), "=r"(rb[bp][1]), "=r"(rb[bp][2]), "=r"(rb[bp][3])
                        : "r"(bd));
                }
                #pragma unroll
                for (int bp = 0; bp < 8; bp++)
                    #pragma unroll
                    for (int hh = 0; hh < 2; hh++) {
                        float* c = s[bp * 2 + hh];
                        asm volatile(
                            "mma.sync.aligned.m16n8k16.row.col.f32.f16.f16.f32 "
                            "{%0,%1,%2,%3}, {%4,%5,%6,%7}, {%8,%9}, {%0,%1,%2,%3};"
                            : "+f"(c[0]), "+f"(c[1]), "+f"(c[2]), "+f"(c[3])
                            : "r"(ra[0]), "r"(ra[1]), "r"(ra[2]), "r"(ra[3]),
                              "r"(rb[bp][hh * 2]), "r"(rb[bp][hh * 2 + 1]));
                    }
            }
        }

        // ---- online softmax ----
        float mj[2] = { -1e30f, -1e30f };
        #pragma unroll
        for (int nt = 0; nt < 16; nt++) {
            mj[0] = fmaxf(mj[0], fmaxf(s[nt][0], s[nt][1]));
            mj[1] = fmaxf(mj[1], fmaxf(s[nt][2], s[nt][3]));
        }
        #pragma unroll
        for (int hh = 0; hh < 2; hh++) {
            mj[hh] = fmaxf(mj[hh], __shfl_xor_sync(0xffffffffu, mj[hh], 1));
            mj[hh] = fmaxf(mj[hh], __shfl_xor_sync(0xffffffffu, mj[hh], 2));
        }
        float mnew[2] = { fmaxf(mrow[0], mj[0]), fmaxf(mrow[1], mj[1]) };
        float corr[2] = { __expf(alpha * (mrow[0] - mnew[0])),
                          __expf(alpha * (mrow[1] - mnew[1])) };
        mrow[0] = mnew[0]; mrow[1] = mnew[1];

        float rs[2] = { 0.f, 0.f };
        uint32_t phA[16], phB[16];
        #pragma unroll
        for (int nt = 0; nt < 16; nt++) {
            float e0 = __expf(alpha * (s[nt][0] - mnew[0]));
            float e1 = __expf(alpha * (s[nt][1] - mnew[0]));
            float e2 = __expf(alpha * (s[nt][2] - mnew[1]));
            float e3 = __expf(alpha * (s[nt][3] - mnew[1]));
            rs[0] += e0 + e1; rs[1] += e2 + e3;
            __half2 p0 = __floats2half2_rn(e0, e1);
            __half2 p1 = __floats2half2_rn(e2, e3);
            phA[nt] = *(uint32_t*)&p0;
            phB[nt] = *(uint32_t*)&p1;
        }
        #pragma unroll
        for (int hh = 0; hh < 2; hh++) {
            rs[hh] += __shfl_xor_sync(0xffffffffu, rs[hh], 1);
            rs[hh] += __shfl_xor_sync(0xffffffffu, rs[hh], 2);
            lrow[hh] = lrow[hh] * corr[hh] + rs[hh];
        }
        #pragma unroll
        for (int nt = 0; nt < 16; nt++) {
            o[nt][0] *= corr[0]; o[nt][1] *= corr[0];
            o[nt][2] *= corr[1]; o[nt][3] *= corr[1];
        }

        // ---- O += P @ V ----
        #pragma unroll
        for (int kc = 0; kc < 8; kc++) {
            uint32_t ra[4] = { phA[kc * 2], phB[kc * 2], phA[kc * 2 + 1], phB[kc * 2 + 1] };
            uint32_t rb[8][4];
            #pragma unroll
            for (int bp = 0; bp < 8; bp++) {
                uint32_t bd = vb + (kc >> 1) * 10240 + (bp * 16 + bRow) * 80 + (kc & 1) * 32 + bK;
                asm volatile("ldmatrix.sync.aligned.m8n8.x4.shared.b16 {%0,%1,%2,%3}, [%4];"
                    : "=r"(rb[bp][0]), "=r"(rb[bp][1]), "=r"(rb[bp][2]), "=r"(rb[bp][3])
                    : "r"(bd));
            }
            #pragma unroll
            for (int bp = 0; bp < 8; bp++)
                #pragma unroll
                for (int hh = 0; hh < 2; hh++) {
                    float* c = o[bp * 2 + hh];
                    asm volatile(
                        "mma.sync.aligned.m16n8k16.row.col.f32.f16.f16.f32 "
                        "{%0,%1,%2,%3}, {%4,%5,%6,%7}, {%8,%9}, {%0,%1,%2,%3};"
                        : "+f"(c[0]), "+f"(c[1]), "+f"(c[2]), "+f"(c[3])
                        : "r"(ra[0]), "r"(ra[1]), "r"(ra[2]), "r"(ra[3]),
                          "r"(rb[bp][hh * 2]), "r"(rb[bp][hh * 2 + 1]));
                }
        }
    }

    // ---- epilogue: O /= l, write fp16 to g_a2 ----
    float inv0 = 1.f / lrow[0], inv1 = 1.f / lrow[1];
    int row0 = m0 + wid * 16 + g;
    #pragma unroll
    for (int nt = 0; nt < 16; nt++) {
        int col = h * 128 + nt * 8 + tig * 2;
        *(__half2*)(g_a2 + (size_t)row0 * N2 + col) =
            __floats2half2_rn(o[nt][0] * inv0, o[nt][1] * inv0);
        *(__half2*)(g_a2 + (size_t)(row0 + 8) * N2 + col) =
            __floats2half2_rn(o[nt][2] * inv1, o[nt][3] * inv1);
    }
}

// ---------------- elementwise ------------------------------------------------
__global__ void gemv_mod_kernel(const float* __restrict__ vec,
                                const float* __restrict__ W, const float* __restrict__ b) {
    int j = blockIdx.x * 8 + (threadIdx.x >> 5);
    int lane = threadIdx.x & 31;
    const float4* w4 = (const float4*)(W + (size_t)j * HID);
    const float4* v4 = (const float4*)vec;
    float acc = 0.f;
    for (int i = lane; i < HID/4; i += 32) {
        float4 w = w4[i], v = v4[i];
        acc += w.x * (v.x / (1.f + __expf(-v.x)));
        acc += w.y * (v.y / (1.f + __expf(-v.y)));
        acc += w.z * (v.z / (1.f + __expf(-v.z)));
        acc += w.w * (v.w / (1.f + __expf(-v.w)));
    }
    #pragma unroll
    for (int o = 16; o; o >>= 1) acc += __shfl_xor_sync(0xffffffffu, acc, o);
    if (lane == 0) g_mod[j] = acc + b[j];
}

__global__ void layernorm_kernel(const float* __restrict__ x) {
    __shared__ float shA[8], shB[8];
    __shared__ float s_mu, s_r;
    int l = blockIdx.x, t = threadIdx.x;
    const float* row = x + (size_t)l * HID;
    float v[12];
    float s = 0.f, ss = 0.f;
    #pragma unroll
    for (int i = 0; i < 12; i++) { v[i] = row[t + i*256]; s += v[i]; ss += v[i]*v[i]; }
    #pragma unroll
    for (int o = 16; o; o >>= 1) {
        s  += __shfl_xor_sync(0xffffffffu, s, o);
        ss += __shfl_xor_sync(0xffffffffu, ss, o);
    }
    if ((t & 31) == 0) { shA[t>>5] = s; shB[t>>5] = ss; }
    __syncthreads();
    if (t == 0) {
        float a = 0.f, bb = 0.f;
        #pragma unroll
        for (int w = 0; w < 8; w++) { a += shA[w]; bb += shB[w]; }
        float mu = a / HID;
        s_mu = mu; s_r = rsqrtf(bb / HID - mu*mu + EPSF);
    }
    __syncthreads();
    float mu = s_mu, r = s_r;
    __half* orow = g_a1 + (size_t)l * HID;
    #pragma unroll
    for (int i = 0; i < 12; i++) {
        int kc = t + i*256;
        float xm = (v[i] - mu) * r * (1.f + g_mod[HID + kc]) + g_mod[kc];
        orow[kc] = __float2half_rn(xm);
    }
}

__global__ void conv_w(const float4* __restrict__ src, uint2* __restrict__ dst, size_t n4) {
    size_t stride = (size_t)gridDim.x * blockDim.x;
    for (size_t i = (size_t)blockIdx.x * blockDim.x + threadIdx.x; i < n4; i += stride) {
        float4 v = src[i];
        __half2 h0 = __floats2half2_rn(v.x, v.y);
        __half2 h1 = __floats2half2_rn(v.z, v.w);
        uint2 u = { *(uint32_t*)&h0, *(uint32_t*)&h1 };
        dst[i] = u;
    }
}

// ---------------- launcher ---------------------------------------------------
extern "C" void kernel_launch(void* const* d_in, const int* in_sizes, int n_in,
                              void* d_out, int out_size) {
    const float* x       = (const float*)d_in[0];
    const float* vec     = (const float*)d_in[1];
    const float* pe      = (const float*)d_in[2];
    const float* mod_w   = (const float*)d_in[3];
    const float* mod_b   = (const float*)d_in[4];
    const float* lin1_w  = (const float*)d_in[5];
    const float* lin1_b  = (const float*)d_in[6];
    const float* lin2_w  = (const float*)d_in[7];
    const float* lin2_b  = (const float*)d_in[8];
    const float* q_scale = (const float*)d_in[9];
    const float* k_scale = (const float*)d_in[10];
    float* out = (float*)d_out;

    void *pa1, *pw1, *pa2, *pw2;
    cudaGetSymbolAddress(&pa1, g_a1);   cudaGetSymbolAddress(&pw1, g_w1);
    cudaGetSymbolAddress(&pa2, g_a2);   cudaGetSymbolAddress(&pw2, g_w2);

    cudaFuncSetAttribute(gemm_h<0>, cudaFuncAttributeMaxDynamicSharedMemorySize, SMEMB);
    cudaFuncSetAttribute(gemm_h<3>, cudaFuncAttributeMaxDynamicSharedMemorySize, SMEMB);
    cudaFuncSetAttribute(flash_attn, cudaFuncAttributeMaxDynamicSharedMemorySize, FA_SMEM);

    gemv_mod_kernel<<<(3*HID)/8, 256>>>(vec, mod_w, mod_b);                 // 1
    layernorm_kernel<<<LEN, 256>>>(x);                                      // 2
    conv_w<<<2048, 256>>>((const float4*)lin1_w, (uint2*)pw1, (size_t)N1*HID/4); // 3

    // 4 (profiled): lin1 M=3072 N=21504 K=3072; epilogue does RMS/RoPE/vT/gelu
    gemm_h<3><<<dim3(LEN/128, N1/128, 1), 256, SMEMB>>>(
        (const __half*)pa1, (const __half*)pw1, lin1_b, nullptr,
        0, HID, pe, q_scale, k_scale, nullptr);

    conv_w<<<2048, 256>>>((const float4*)lin2_w, (uint2*)pw2, (size_t)HID*N2/4); // 5

    // 6: fused attention -> g_a2[:, h*128+d]
    flash_attn<<<dim3(LEN/128, NH), 256, FA_SMEM>>>();

    // 7: lin2 M=3072 N=3072 K=15360 -> out = x + gate*(acc+bias)
    gemm_h<0><<<dim3(LEN/128, HID/128, 1), 256, SMEMB>>>(
        (const __half*)pa2, (const __half*)pw2, lin2_b, out,
        HID, N2, nullptr, nullptr, nullptr, x);
}

// round 11
// speedup vs baseline: 1.5362x; 1.1799x over previous
#include <cuda_runtime.h>
#include <cuda_fp16.h>
#include <math.h>
#include <stdint.h>

#define LEN   3072
#define HID   3072
#define NH    24
#define HD    128
#define MLPD  12288
#define N1    (3*HID + MLPD)   // 21504
#define N2    (HID + MLPD)     // 15360
#define NQKV  (3*HID)          // 9216
#define EPSF  1e-6f

// ---------------- scratch ----------------------------------------------------
__device__ float g_mod[3*HID];
__device__ __align__(256) __half g_a1[(size_t)LEN*HID];
__device__ __align__(256) __half g_w1[(size_t)N1*HID];
__device__ __align__(256) __half g_a2[(size_t)LEN*N2];          // [attn | gelu(mlp)]
__device__ __align__(256) __half g_w2[(size_t)HID*N2];
__device__ __align__(256) __half g_qh[(size_t)NH*LEN*HD];
__device__ __align__(256) __half g_kh[(size_t)NH*LEN*HD];
__device__ __align__(256) __half g_vT[(size_t)NH*HD*LEN];       // [h][d][l]

__device__ __forceinline__ uint32_t smem_u32(const void* p) {
    uint32_t a;
    asm("{ .reg .u64 t; cvta.to.shared.u64 t, %1; cvt.u32.u64 %0, t; }" : "=r"(a) : "l"(p));
    return a;
}

// ------- fp16 HMMA GEMM: 128x128 tile, 4 warps (2x2) of 64x64, 2 CTA/SM -----
#define PITCH 80
#define ATILE (128*PITCH)
#define STGSZ (2*ATILE)
#define NSTG  3
#define SMEMB (NSTG*STGSZ)            // 61440

// EPI: 0 = lin2: fp32 out = xres + gate*(acc+bias)
//      3 = lin1: q/k tiles -> RMS+RoPE -> g_qh/g_kh; v tiles -> transpose -> g_vT;
//          mlp tiles -> gelu -> g_a2
template<int EPI>
__global__ void __launch_bounds__(128, 2) gemm_h(
    const __half* __restrict__ A, const __half* __restrict__ B,
    const float* __restrict__ bias, void* __restrict__ Cv,
    int ldC, int K,
    const float* __restrict__ pe, const float* __restrict__ qsc,
    const float* __restrict__ ksc, const float* __restrict__ xres)
{
    extern __shared__ char smem[];
    const uint32_t sb = smem_u32(smem);
    const int tid = threadIdx.x, lane = tid & 31, wid = tid >> 5;
    const int wm = wid & 1, wn = wid >> 1;            // 2m x 2n warps, 64x64 each
    const int m0 = blockIdx.x * 128, n0 = blockIdx.y * 128;
    const int KT = K >> 5;

    auto load_stage = [&](int buf, int kt) {
        const int k0 = kt << 5;
        #pragma unroll
        for (int i = 0; i < 8; i++) {                 // 1024 chunks / 128 thr
            int idx = tid + (i << 7);
            int isB = idx >> 9;
            int r = (idx & 511) >> 2, ch = idx & 3;
            const __half* src = (isB ? B + (size_t)(n0 + r) * K
                                     : A + (size_t)(m0 + r) * K) + k0 + ch * 8;
            uint32_t dst = sb + buf * STGSZ + isB * ATILE + r * PITCH + ch * 16;
            asm volatile("cp.async.cg.shared.global [%0], [%1], 16;"
                         :: "r"(dst), "l"(src) : "memory");
        }
    };

    float acc[4][8][4];
    #pragma unroll
    for (int a = 0; a < 4; a++)
        #pragma unroll
        for (int b = 0; b < 8; b++)
            #pragma unroll
            for (int c = 0; c < 4; c++) acc[a][b][c] = 0.f;

    const int aRow = (lane & 7) + ((lane >> 3) & 1) * 8, aK = (lane >> 4) * 16;
    const int bRow = (lane & 7) + (lane >> 4) * 8,       bK = ((lane >> 3) & 1) * 16;
    const uint32_t aAdr0 = (uint32_t)((wm * 64 + aRow) * PITCH + aK);
    const uint32_t bAdr0 = (uint32_t)(ATILE + (wn * 64 + bRow) * PITCH + bK);

    load_stage(0, 0);
    asm volatile("cp.async.commit_group;" ::: "memory");
    if (KT > 1) load_stage(1, 1);
    asm volatile("cp.async.commit_group;" ::: "memory");

    for (int kt = 0; kt < KT; kt++) {
        asm volatile("cp.async.wait_group 1;" ::: "memory");
        __syncthreads();
        int nk = kt + 2;
        if (nk < KT) load_stage(nk % NSTG, nk);
        asm volatile("cp.async.commit_group;" ::: "memory");

        const uint32_t base = sb + (kt % NSTG) * STGSZ;
        #pragma unroll
        for (int ks = 0; ks < 2; ks++) {
            uint32_t ra[4][4], rb[4][4];
            #pragma unroll
            for (int mt = 0; mt < 4; mt++) {
                uint32_t ad = base + aAdr0 + mt * (16 * PITCH) + ks * 32;
                asm volatile("ldmatrix.sync.aligned.m8n8.x4.shared.b16 {%0,%1,%2,%3}, [%4];"
                    : "=r"(ra[mt][0]), "=r"(ra[mt][1]), "=r"(ra[mt][2]), "=r"(ra[mt][3])
                    : "r"(ad));
            }
            #pragma unroll
            for (int nt = 0; nt < 4; nt++) {
                uint32_t bd = base + bAdr0 + nt * (16 * PITCH) + ks * 32;
                asm volatile("ldmatrix.sync.aligned.m8n8.x4.shared.b16 {%0,%1,%2,%3}, [%4];"
                    : "=r"(rb[nt][0]), "=r"(rb[nt][1]), "=r"(rb[nt][2]), "=r"(rb[nt][3])
                    : "r"(bd));
            }
            #pragma unroll
            for (int mt = 0; mt < 4; mt++)
                #pragma unroll
                for (int nt = 0; nt < 4; nt++) {
                    #pragma unroll
                    for (int h = 0; h < 2; h++) {
                        float* c = acc[mt][nt * 2 + h];
                        asm volatile(
                            "mma.sync.aligned.m16n8k16.row.col.f32.f16.f16.f32 "
                            "{%0,%1,%2,%3}, {%4,%5,%6,%7}, {%8,%9}, {%0,%1,%2,%3};"
                            : "+f"(c[0]), "+f"(c[1]), "+f"(c[2]), "+f"(c[3])
                            : "r"(ra[mt][0]), "r"(ra[mt][1]), "r"(ra[mt][2]), "r"(ra[mt][3]),
                              "r"(rb[nt][h * 2]), "r"(rb[nt][h * 2 + 1]));
                    }
                }
        }
        __syncthreads();
    }

    const int g = lane >> 2, tig = lane & 3;

    if (EPI == 3 && n0 < NQKV) {
        asm volatile("cp.async.wait_group 0;" ::: "memory");
        __syncthreads();
        if (n0 < 2 * HID) {
            // ---- q or k tile: bias + RMS + RoPE + fp16 store ----
            const bool isq = (n0 < HID);
            const int h = (n0 - (isq ? 0 : HID)) >> 7;
            const float* sc = isq ? qsc : ksc;
            __half* dbuf = isq ? g_qh : g_kh;
            float* rsum = (float*)smem;                      // [128][2]
            float ss[4][2];
            #pragma unroll
            for (int mt = 0; mt < 4; mt++) { ss[mt][0] = 0.f; ss[mt][1] = 0.f; }
            #pragma unroll
            for (int mt = 0; mt < 4; mt++)
                #pragma unroll
                for (int j = 0; j < 8; j++) {
                    int col = wn * 64 + j * 8 + tig * 2;
                    float b0 = bias[n0 + col], b1 = bias[n0 + col + 1];
                    float t00 = acc[mt][j][0] + b0, t01 = acc[mt][j][1] + b1;
                    float t10 = acc[mt][j][2] + b0, t11 = acc[mt][j][3] + b1;
                    ss[mt][0] += t00 * t00 + t01 * t01;
                    ss[mt][1] += t10 * t10 + t11 * t11;
                }
            #pragma unroll
            for (int mt = 0; mt < 4; mt++)
                #pragma unroll
                for (int hh = 0; hh < 2; hh++) {
                    float v = ss[mt][hh];
                    v += __shfl_xor_sync(0xffffffffu, v, 1);
                    v += __shfl_xor_sync(0xffffffffu, v, 2);
                    if (tig == 0) rsum[(wm * 64 + mt * 16 + g + hh * 8) * 2 + wn] = v;
                }
            __syncthreads();
            float rr[4][2];
            #pragma unroll
            for (int mt = 0; mt < 4; mt++)
                #pragma unroll
                for (int hh = 0; hh < 2; hh++) {
                    int lr = wm * 64 + mt * 16 + g + hh * 8;
                    rr[mt][hh] = rsqrtf((rsum[lr * 2] + rsum[lr * 2 + 1]) * (1.f / HD) + EPSF);
                }
            #pragma unroll
            for (int mt = 0; mt < 4; mt++)
                #pragma unroll
                for (int j = 0; j < 8; j++) {
                    int d = wn * 64 + j * 8 + tig * 2;
                    float b0 = bias[n0 + d], b1 = bias[n0 + d + 1];
                    float s0 = sc[d], s1 = sc[d + 1];
                    #pragma unroll
                    for (int hh = 0; hh < 2; hh++) {
                        int lr = wm * 64 + mt * 16 + g + hh * 8;
                        int l = m0 + lr;
                        float t0 = (acc[mt][j][hh * 2]     + b0) * rr[mt][hh] * s0;
                        float t1 = (acc[mt][j][hh * 2 + 1] + b1) * rr[mt][hh] * s1;
                        float4 p = *(const float4*)(pe + (size_t)l * 256 + d * 2);
                        float o0 = p.x * t0 + p.y * t1;
                        float o1 = p.z * t0 + p.w * t1;
                        *(__half2*)(dbuf + ((size_t)h * LEN + l) * HD + d) =
                            __floats2half2_rn(o0, o1);
                    }
                }
        } else {
            // ---- v tile: bias + fp16, smem transpose -> g_vT ----
            const int h = (n0 - 2 * HID) >> 7;
            __half* vs = (__half*)smem;                      // [128][136]
            #pragma unroll
            for (int mt = 0; mt < 4; mt++)
                #pragma unroll
                for (int j = 0; j < 8; j++) {
                    int d = wn * 64 + j * 8 + tig * 2;
                    float b0 = bias[n0 + d], b1 = bias[n0 + d + 1];
                    #pragma unroll
                    for (int hh = 0; hh < 2; hh++) {
                        int lr = wm * 64 + mt * 16 + g + hh * 8;
                        *(__half2*)(vs + lr * 136 + d) =
                            __floats2half2_rn(acc[mt][j][hh * 2] + b0,
                                              acc[mt][j][hh * 2 + 1] + b1);
                    }
                }
            __syncthreads();
            int d = tid;                                     // 0..127
            __align__(16) __half tmp[128];
            #pragma unroll
            for (int i = 0; i < 128; i++) tmp[i] = vs[i * 136 + d];
            __half* dst = g_vT + ((size_t)h * HD + d) * LEN + m0;
            #pragma unroll
            for (int i = 0; i < 16; i++)
                *(uint4*)(dst + i * 8) = *(uint4*)(tmp + i * 8);
        }
        return;
    }

    #pragma unroll
    for (int mt = 0; mt < 4; mt++) {
        #pragma unroll
        for (int j = 0; j < 8; j++) {
            int row = m0 + wm * 64 + mt * 16 + g;
            int col = n0 + wn * 64 + j * 8 + tig * 2;
            float v00 = acc[mt][j][0], v01 = acc[mt][j][1];
            float v10 = acc[mt][j][2], v11 = acc[mt][j][3];
            if (EPI == 0) {
                float b0 = bias[col], b1 = bias[col + 1];
                float g0 = g_mod[2 * HID + col], g1 = g_mod[2 * HID + col + 1];
                float* C = (float*)Cv;
                float2 x0 = *(const float2*)(xres + (size_t)row * HID + col);
                float2 x1 = *(const float2*)(xres + (size_t)(row + 8) * HID + col);
                float2 a0 = { x0.x + g0 * (v00 + b0), x0.y + g1 * (v01 + b1) };
                float2 a1 = { x1.x + g0 * (v10 + b0), x1.y + g1 * (v11 + b1) };
                *(float2*)(C + (size_t)row * ldC + col) = a0;
                *(float2*)(C + (size_t)(row + 8) * ldC + col) = a1;
            } else {  // EPI == 3, mlp tile
                float b0 = bias[col], b1 = bias[col + 1];
                v00 += b0; v01 += b1; v10 += b0; v11 += b1;
                auto gelu = [](float v) {
                    float inr = 0.7978845608028654f * (v + 0.044715f * v * v * v);
                    return 0.5f * v * (1.f + tanhf(inr));
                };
                int c2 = HID + (col - NQKV);
                *(__half2*)(g_a2 + (size_t)row * N2 + c2) = __floats2half2_rn(gelu(v00), gelu(v01));
                *(__half2*)(g_a2 + (size_t)(row + 8) * N2 + c2) = __floats2half2_rn(gelu(v10), gelu(v11));
            }
        }
    }
}

// ---------------- flash attention (unchanged from R10) -----------------------
#define FA_Q    0
#define FA_KV   40960
#define FA_KVSZ 81920
#define FA_SMEM 204800
#define NKT     (LEN/128)      // 24

__global__ void __launch_bounds__(256, 1) flash_attn() {
    extern __shared__ char smem[];
    const uint32_t sb = smem_u32(smem);
    const int tid = threadIdx.x, lane = tid & 31, wid = tid >> 5;
    const int g = lane >> 2, tig = lane & 3;
    const int m0 = blockIdx.x * 128;
    const int h = blockIdx.y;
    const float alpha = 0.08838834764831845f;

    #pragma unroll
    for (int i = 0; i < 8; i++) {
        int q = tid + (i << 8);
        int r = q >> 4, c = q & 15;
        const __half* src = g_qh + ((size_t)h * LEN + m0 + r) * HD + c * 8;
        uint32_t dst = sb + FA_Q + (c >> 2) * 10240 + r * 80 + (c & 3) * 16;
        asm volatile("cp.async.cg.shared.global [%0], [%1], 16;" :: "r"(dst), "l"(src) : "memory");
    }
    auto load_kv = [&](int j, int buf) {
        #pragma unroll
        for (int i = 0; i < 16; i++) {
            int idx = tid + (i << 8);
            int isV = idx >> 11;
            int e = idx & 2047;
            int r = e >> 4, c = e & 15;
            const __half* src = isV
                ? g_vT + ((size_t)h * HD + r) * LEN + j * 128 + c * 8
                : g_kh + ((size_t)h * LEN + j * 128 + r) * HD + c * 8;
            uint32_t dst = sb + FA_KV + buf * FA_KVSZ + isV * 40960
                         + (c >> 2) * 10240 + r * 80 + (c & 3) * 16;
            asm volatile("cp.async.cg.shared.global [%0], [%1], 16;" :: "r"(dst), "l"(src) : "memory");
        }
    };
    load_kv(0, 0);
    asm volatile("cp.async.commit_group;" ::: "memory");

    float o[16][4];
    #pragma unroll
    for (int a = 0; a < 16; a++)
        #pragma unroll
        for (int b = 0; b < 4; b++) o[a][b] = 0.f;
    float mrow[2] = { -1e30f, -1e30f };
    float lrow[2] = { 0.f, 0.f };

    const int aRow = (lane & 7) + ((lane >> 3) & 1) * 8, aK = (lane >> 4) * 16;
    const int bRow = (lane & 7) + (lane >> 4) * 8,       bK = ((lane >> 3) & 1) * 16;
    const uint32_t qAdr = (uint32_t)((wid * 16 + aRow) * 80 + aK);

    for (int j = 0; j < NKT; j++) {
        __syncthreads();
        if (j + 1 < NKT) load_kv(j + 1, (j + 1) & 1);
        asm volatile("cp.async.commit_group;" ::: "memory");
        asm volatile("cp.async.wait_group 1;" ::: "memory");
        __syncthreads();

        const uint32_t kb = sb + FA_KV + (j & 1) * FA_KVSZ;
        const uint32_t vb = kb + 40960;

        float s[16][4];
        #pragma unroll
        for (int a = 0; a < 16; a++)
            #pragma unroll
            for (int b = 0; b < 4; b++) s[a][b] = 0.f;
        #pragma unroll
        for (int kc = 0; kc < 4; kc++) {
            #pragma unroll
            for (int ks = 0; ks < 2; ks++) {
                uint32_t ra[4], rb[8][4];
                uint32_t ad = sb + FA_Q + kc * 10240 + qAdr + ks * 32;
                asm volatile("ldmatrix.sync.aligned.m8n8.x4.shared.b16 {%0,%1,%2,%3}, [%4];"
                    : "=r"(ra[0]), "=r"(ra[1]), "=r"(ra[2]), "=r"(ra[3]) : "r"(ad));
                #pragma unroll
                for (int bp = 0; bp < 8; bp++) {
                    uint32_t bd = kb + kc * 10240 + (bp * 16 + bRow) * 80 + ks * 32 + bK;
                    asm volatile("ldmatrix.sync.aligned.m8n8.x4.shared.b16 {%0,%1,%2,%3}, [%4];"
                        : "=r"(rb[bp][0]), "=r"(rb[bp][1]), "=r"(rb[bp][2]), "=r"(rb[bp][3])
                        : "r"(bd));
                }
                #pragma unroll
                for (int bp = 0; bp < 8; bp++)
                    #pragma unroll
                    for (int hh = 0; hh < 2; hh++) {
                        float* c = s[bp * 2 + hh];
                        asm volatile(
                            "mma.sync.aligned.m16n8k16.row.col.f32.f16.f16.f32 "
                            "{%0,%1,%2,%3}, {%4,%5,%6,%7}, {%8,%9}, {%0,%1,%2,%3};"
                            : "+f"(c[0]), "+f"(c[1]), "+f"(c[2]), "+f"(c[3])
                            : "r"(ra[0]), "r"(ra[1]), "r"(ra[2]), "r"(ra[3]),
                              "r"(rb[bp][hh * 2]), "r"(rb[bp][hh * 2 + 1]));
                    }
            }
        }

        float mj[2] = { -1e30f, -1e30f };
        #pragma unroll
        for (int nt = 0; nt < 16; nt++) {
            mj[0] = fmaxf(mj[0], fmaxf(s[nt][0], s[nt][1]));
            mj[1] = fmaxf(mj[1], fmaxf(s[nt][2], s[nt][3]));
        }
        #pragma unroll
        for (int hh = 0; hh < 2; hh++) {
            mj[hh] = fmaxf(mj[hh], __shfl_xor_sync(0xffffffffu, mj[hh], 1));
            mj[hh] = fmaxf(mj[hh], __shfl_xor_sync(0xffffffffu, mj[hh], 2));
        }
        float mnew[2] = { fmaxf(mrow[0], mj[0]), fmaxf(mrow[1], mj[1]) };
        float corr[2] = { __expf(alpha * (mrow[0] - mnew[0])),
                          __expf(alpha * (mrow[1] - mnew[1])) };
        mrow[0] = mnew[0]; mrow[1] = mnew[1];

        float rs[2] = { 0.f, 0.f };
        uint32_t phA[16], phB[16];
        #pragma unroll
        for (int nt = 0; nt < 16; nt++) {
            float e0 = __expf(alpha * (s[nt][0] - mnew[0]));
            float e1 = __expf(alpha * (s[nt][1] - mnew[0]));
            float e2 = __expf(alpha * (s[nt][2] - mnew[1]));
            float e3 = __expf(alpha * (s[nt][3] - mnew[1]));
            rs[0] += e0 + e1; rs[1] += e2 + e3;
            __half2 p0 = __floats2half2_rn(e0, e1);
            __half2 p1 = __floats2half2_rn(e2, e3);
            phA[nt] = *(uint32_t*)&p0;
            phB[nt] = *(uint32_t*)&p1;
        }
        #pragma unroll
        for (int hh = 0; hh < 2; hh++) {
            rs[hh] += __shfl_xor_sync(0xffffffffu, rs[hh], 1);
            rs[hh] += __shfl_xor_sync(0xffffffffu, rs[hh], 2);
            lrow[hh] = lrow[hh] * corr[hh] + rs[hh];
        }
        #pragma unroll
        for (int nt = 0; nt < 16; nt++) {
            o[nt][0] *= corr[0]; o[nt][1] *= corr[0];
            o[nt][2] *= corr[1]; o[nt][3] *= corr[1];
        }

        #pragma unroll
        for (int kc = 0; kc < 8; kc++) {
            uint32_t ra[4] = { phA[kc * 2], phB[kc * 2], phA[kc * 2 + 1], phB[kc * 2 + 1] };
            uint32_t rb[8][4];
            #pragma unroll
            for (int bp = 0; bp < 8; bp++) {
                uint32_t bd = vb + (kc >> 1) * 10240 + (bp * 16 + bRow) * 80 + (kc & 1) * 32 + bK;
                asm volatile("ldmatrix.sync.aligned.m8n8.x4.shared.b16 {%0,%1,%2,%3}, [%4];"
                    : "=r"(rb[bp][0]), "=r"(rb[bp][1]), "=r"(rb[bp][2]), "=r"(rb[bp][3])
                    : "r"(bd));
            }
            #pragma unroll
            for (int bp = 0; bp < 8; bp++)
                #pragma unroll
                for (int hh = 0; hh < 2; hh++) {
                    float* c = o[bp * 2 + hh];
                    asm volatile(
                        "mma.sync.aligned.m16n8k16.row.col.f32.f16.f16.f32 "
                        "{%0,%1,%2,%3}, {%4,%5,%6,%7}, {%8,%9}, {%0,%1,%2,%3};"
                        : "+f"(c[0]), "+f"(c[1]), "+f"(c[2]), "+f"(c[3])
                        : "r"(ra[0]), "r"(ra[1]), "r"(ra[2]), "r"(ra[3]),
                          "r"(rb[bp][hh * 2]), "r"(rb[bp][hh * 2 + 1]));
                }
        }
    }

    float inv0 = 1.f / lrow[0], inv1 = 1.f / lrow[1];
    int row0 = m0 + wid * 16 + g;
    #pragma unroll
    for (int nt = 0; nt < 16; nt++) {
        int col = h * 128 + nt * 8 + tig * 2;
        *(__half2*)(g_a2 + (size_t)row0 * N2 + col) =
            __floats2half2_rn(o[nt][0] * inv0, o[nt][1] * inv0);
        *(__half2*)(g_a2 + (size_t)(row0 + 8) * N2 + col) =
            __floats2half2_rn(o[nt][2] * inv1, o[nt][3] * inv1);
    }
}

// ---------------- elementwise ------------------------------------------------
__global__ void gemv_mod_kernel(const float* __restrict__ vec,
                                const float* __restrict__ W, const float* __restrict__ b) {
    int j = blockIdx.x * 8 + (threadIdx.x >> 5);
    int lane = threadIdx.x & 31;
    const float4* w4 = (const float4*)(W + (size_t)j * HID);
    const float4* v4 = (const float4*)vec;
    float acc = 0.f;
    for (int i = lane; i < HID/4; i += 32) {
        float4 w = w4[i], v = v4[i];
        acc += w.x * (v.x / (1.f + __expf(-v.x)));
        acc += w.y * (v.y / (1.f + __expf(-v.y)));
        acc += w.z * (v.z / (1.f + __expf(-v.z)));
        acc += w.w * (v.w / (1.f + __expf(-v.w)));
    }
    #pragma unroll
    for (int o = 16; o; o >>= 1) acc += __shfl_xor_sync(0xffffffffu, acc, o);
    if (lane == 0) g_mod[j] = acc + b[j];
}

__global__ void layernorm_kernel(const float* __restrict__ x) {
    __shared__ float shA[8], shB[8];
    __shared__ float s_mu, s_r;
    int l = blockIdx.x, t = threadIdx.x;
    const float* row = x + (size_t)l * HID;
    float v[12];
    float s = 0.f, ss = 0.f;
    #pragma unroll
    for (int i = 0; i < 12; i++) { v[i] = row[t + i*256]; s += v[i]; ss += v[i]*v[i]; }
    #pragma unroll
    for (int o = 16; o; o >>= 1) {
        s  += __shfl_xor_sync(0xffffffffu, s, o);
        ss += __shfl_xor_sync(0xffffffffu, ss, o);
    }
    if ((t & 31) == 0) { shA[t>>5] = s; shB[t>>5] = ss; }
    __syncthreads();
    if (t == 0) {
        float a = 0.f, bb = 0.f;
        #pragma unroll
        for (int w = 0; w < 8; w++) { a += shA[w]; bb += shB[w]; }
        float mu = a / HID;
        s_mu = mu; s_r = rsqrtf(bb / HID - mu*mu + EPSF);
    }
    __syncthreads();
    float mu = s_mu, r = s_r;
    __half* orow = g_a1 + (size_t)l * HID;
    #pragma unroll
    for (int i = 0; i < 12; i++) {
        int kc = t + i*256;
        float xm = (v[i] - mu) * r * (1.f + g_mod[HID + kc]) + g_mod[kc];
        orow[kc] = __float2half_rn(xm);
    }
}

__global__ void conv_w(const float4* __restrict__ src, uint2* __restrict__ dst, size_t n4) {
    size_t stride = (size_t)gridDim.x * blockDim.x;
    for (size_t i = (size_t)blockIdx.x * blockDim.x + threadIdx.x; i < n4; i += stride) {
        float4 v = src[i];
        __half2 h0 = __floats2half2_rn(v.x, v.y);
        __half2 h1 = __floats2half2_rn(v.z, v.w);
        uint2 u = { *(uint32_t*)&h0, *(uint32_t*)&h1 };
        dst[i] = u;
    }
}

// ---------------- launcher ---------------------------------------------------
extern "C" void kernel_launch(void* const* d_in, const int* in_sizes, int n_in,
                              void* d_out, int out_size) {
    const float* x       = (const float*)d_in[0];
    const float* vec     = (const float*)d_in[1];
    const float* pe      = (const float*)d_in[2];
    const float* mod_w   = (const float*)d_in[3];
    const float* mod_b   = (const float*)d_in[4];
    const float* lin1_w  = (const float*)d_in[5];
    const float* lin1_b  = (const float*)d_in[6];
    const float* lin2_w  = (const float*)d_in[7];
    const float* lin2_b  = (const float*)d_in[8];
    const float* q_scale = (const float*)d_in[9];
    const float* k_scale = (const float*)d_in[10];
    float* out = (float*)d_out;

    void *pa1, *pw1, *pa2, *pw2;
    cudaGetSymbolAddress(&pa1, g_a1);   cudaGetSymbolAddress(&pw1, g_w1);
    cudaGetSymbolAddress(&pa2, g_a2);   cudaGetSymbolAddress(&pw2, g_w2);

    cudaFuncSetAttribute(gemm_h<0>, cudaFuncAttributeMaxDynamicSharedMemorySize, SMEMB);
    cudaFuncSetAttribute(gemm_h<3>, cudaFuncAttributeMaxDynamicSharedMemorySize, SMEMB);
    cudaFuncSetAttribute(flash_attn, cudaFuncAttributeMaxDynamicSharedMemorySize, FA_SMEM);

    gemv_mod_kernel<<<(3*HID)/8, 256>>>(vec, mod_w, mod_b);                 // 1
    layernorm_kernel<<<LEN, 256>>>(x);                                      // 2
    conv_w<<<2048, 256>>>((const float4*)lin1_w, (uint2*)pw1, (size_t)N1*HID/4); // 3

    // 4 (profiled): lin1 M=3072 N=21504 K=3072; epilogue does RMS/RoPE/vT/gelu
    gemm_h<3><<<dim3(LEN/128, N1/128, 1), 128, SMEMB>>>(
        (const __half*)pa1, (const __half*)pw1, lin1_b, nullptr,
        0, HID, pe, q_scale, k_scale, nullptr);

    conv_w<<<2048, 256>>>((const float4*)lin2_w, (uint2*)pw2, (size_t)HID*N2/4); // 5

    // 6: fused attention -> g_a2[:, h*128+d]
    flash_attn<<<dim3(LEN/128, NH), 256, FA_SMEM>>>();

    // 7: lin2 M=3072 N=3072 K=15360 -> out = x + gate*(acc+bias)
    gemm_h<0><<<dim3(LEN/128, HID/128, 1), 128, SMEMB>>>(
        (const __half*)pa2, (const __half*)pw2, lin2_b, out,
        HID, N2, nullptr, nullptr, nullptr, x);
}